// round 9
// baseline (speedup 1.0000x reference)
#include <cuda_runtime.h>
#include <cuda_bf16.h>
#include <cstdint>

#define BB 2
#define CC 256
#define NHEAD 4
#define HD 64
#define NTOK 4096

// ---------------- device scratch ----------------
__device__ __nv_bfloat16 g_xq[BB*NTOK*CC];         // GN(input)^T  [b][tok][ch]
__device__ __nv_bfloat16 g_xk[BB*NTOK*CC];         // GN(c)^T      [b][tok][ch]
__device__ __nv_bfloat16 g_qb[BB*NHEAD*NTOK*HD];   // [bh][tok][d]  (pre-scaled by CEXP)
__device__ __nv_bfloat16 g_kb[BB*NHEAD*NTOK*HD];   // [bh][tok][d]
__device__ __nv_bfloat16 g_vb[BB*NHEAD*HD*NTOK];   // [bh][d][tok]
__device__ __nv_bfloat16 g_ob[BB*NTOK*CC];         // attn out     [b][tok][ch]

// ---------------- helpers ----------------
__device__ __forceinline__ void mma16816(float* c, uint32_t a0, uint32_t a1, uint32_t a2,
                                         uint32_t a3, uint32_t b0, uint32_t b1) {
    asm volatile(
        "mma.sync.aligned.m16n8k16.row.col.f32.bf16.bf16.f32 "
        "{%0,%1,%2,%3}, {%4,%5,%6,%7}, {%8,%9}, {%0,%1,%2,%3};"
        : "+f"(c[0]), "+f"(c[1]), "+f"(c[2]), "+f"(c[3])
        : "r"(a0), "r"(a1), "r"(a2), "r"(a3), "r"(b0), "r"(b1));
}
__device__ __forceinline__ float ex2(float x) {
    float r;
    asm("ex2.approx.ftz.f32 %0, %1;" : "=f"(r) : "f"(x));
    return r;
}
__device__ __forceinline__ uint32_t pack_bf16(float lo, float hi) {
    uint32_t r;
    asm("cvt.rn.bf16x2.f32 %0, %1, %2;" : "=r"(r) : "f"(hi), "f"(lo));
    return r;
}
__device__ __forceinline__ uint32_t smem_u32(const void* p) {
    uint32_t a;
    asm("{ .reg .u64 t; cvta.to.shared.u64 t, %1; cvt.u32.u64 %0, t; }" : "=r"(a) : "l"(p));
    return a;
}
__device__ __forceinline__ void ldsm_x4(uint32_t& r0, uint32_t& r1, uint32_t& r2, uint32_t& r3,
                                        uint32_t addr) {
    asm volatile("ldmatrix.sync.aligned.m8n8.x4.shared.b16 {%0,%1,%2,%3}, [%4];"
                 : "=r"(r0), "=r"(r1), "=r"(r2), "=r"(r3) : "r"(addr));
}
__device__ __forceinline__ void cp16(uint32_t saddr, const void* g) {
    asm volatile("cp.async.cg.shared.global [%0], [%1], 16;" :: "r"(saddr), "l"(g));
}
#define CP_COMMIT() asm volatile("cp.async.commit_group;" ::: "memory")
#define CP_WAIT(n)  asm volatile("cp.async.wait_group %0;" :: "n"(n) : "memory")

// ---------------- GroupNorm -> bf16 X^T [b][tok][256] ----------------
__global__ __launch_bounds__(256) void gn_xt_kernel(const float* __restrict__ src,
                                                    const float* __restrict__ gw,
                                                    const float* __restrict__ gb,
                                                    int which) {
    int b = blockIdx.x >> 5, g = blockIdx.x & 31;
    size_t base = ((size_t)b * CC + g * 8) * NTOK;
    const float4* s4 = reinterpret_cast<const float4*>(src + base);
    int tid = threadIdx.x;

    float sum = 0.f, ssq = 0.f;
#pragma unroll
    for (int i = 0; i < 32; i++) {
        float4 v = s4[tid + i * 256];
        sum += v.x + v.y + v.z + v.w;
        ssq += v.x * v.x + v.y * v.y + v.z * v.z + v.w * v.w;
    }
#pragma unroll
    for (int off = 16; off; off >>= 1) {
        sum += __shfl_xor_sync(0xffffffffu, sum, off);
        ssq += __shfl_xor_sync(0xffffffffu, ssq, off);
    }
    __shared__ float r1[8], r2[8];
    if ((tid & 31) == 0) { r1[tid >> 5] = sum; r2[tid >> 5] = ssq; }
    __syncthreads();
    sum = 0.f; ssq = 0.f;
#pragma unroll
    for (int i = 0; i < 8; i++) { sum += r1[i]; ssq += r2[i]; }
    float mean = sum * (1.f / 32768.f);
    float var  = ssq * (1.f / 32768.f) - mean * mean;
    float rstd = rsqrtf(var + 1e-5f);

    float a[8], c0[8];
#pragma unroll
    for (int ch = 0; ch < 8; ch++) {
        a[ch]  = gw[g * 8 + ch] * rstd;
        c0[ch] = gb[g * 8 + ch] - mean * a[ch];
    }
    __nv_bfloat16* xt = (which ? g_xk : g_xq) + (size_t)b * NTOK * CC + g * 8;
#pragma unroll
    for (int i = 0; i < 16; i++) {
        int tok = tid + i * 256;
        float v[8];
#pragma unroll
        for (int ch = 0; ch < 8; ch++)
            v[ch] = src[base + (size_t)ch * NTOK + tok] * a[ch] + c0[ch];
        uint4 u = {pack_bf16(v[0], v[1]), pack_bf16(v[2], v[3]),
                   pack_bf16(v[4], v[5]), pack_bf16(v[6], v[7])};
        *reinterpret_cast<uint4*>(xt + (size_t)tok * CC) = u;
    }
}

// ---------------- QKV projection via HMMA (q pre-scaled by CEXP) ----------------
__global__ __launch_bounds__(256) void qkv_kernel(const float* __restrict__ wq,
                                                  const float* __restrict__ wkv) {
    __shared__ __nv_bfloat16 XTs[128 * 72];
    __shared__ __nv_bfloat16 Ws[64 * 72];

    int tid = threadIdx.x, wid = tid >> 5, lane = tid & 31;
    int r0 = lane >> 2, cp = (lane & 3) << 1;
    int nx = blockIdx.x, role = blockIdx.y, b = blockIdx.z;

    const float* W;
    const __nv_bfloat16* X;
    int h;
    bool is_v = (role >= 8);
    if (role < 4)      { h = role;     W = wq  + (size_t)h * 64 * CC;          X = g_xq + (size_t)b * NTOK * CC; }
    else if (role < 8) { h = role - 4; W = wkv + (size_t)(h * 128) * CC;       X = g_xk + (size_t)b * NTOK * CC; }
    else               { h = role - 8; W = wkv + (size_t)(h * 128 + 64) * CC;  X = g_xk + (size_t)b * NTOK * CC; }
    int bh = b * NHEAD + h;

    float acc[8][4] = {};

    for (int k0 = 0; k0 < CC; k0 += 64) {
#pragma unroll
        for (int i = 0; i < 4; i++) {
            int idx = tid + i * 256;
            int r = idx >> 4, c4 = (idx & 15) << 2;
            float4 w4 = *reinterpret_cast<const float4*>(W + (size_t)r * CC + k0 + c4);
            *reinterpret_cast<uint32_t*>(&Ws[r * 72 + c4])     = pack_bf16(w4.x, w4.y);
            *reinterpret_cast<uint32_t*>(&Ws[r * 72 + c4 + 2]) = pack_bf16(w4.z, w4.w);
        }
#pragma unroll
        for (int i = 0; i < 4; i++) {
            int idx = tid + i * 256;
            int r = idx >> 3, c8 = idx & 7;
            *reinterpret_cast<uint4*>(&XTs[r * 72 + c8 * 8]) =
                *reinterpret_cast<const uint4*>(X + ((size_t)(nx * 128 + r)) * CC + k0 + c8 * 8);
        }
        __syncthreads();

        if (!is_v) {
#pragma unroll
            for (int ks = 0; ks < 4; ks++) {
                const __nv_bfloat16* Ar = XTs + (wid * 16 + r0) * 72 + ks * 16 + cp;
                uint32_t a0 = *reinterpret_cast<const uint32_t*>(Ar);
                uint32_t a1 = *reinterpret_cast<const uint32_t*>(Ar + 8 * 72);
                uint32_t a2 = *reinterpret_cast<const uint32_t*>(Ar + 8);
                uint32_t a3 = *reinterpret_cast<const uint32_t*>(Ar + 8 * 72 + 8);
#pragma unroll
                for (int nt = 0; nt < 8; nt++) {
                    const __nv_bfloat16* Br = Ws + (nt * 8 + r0) * 72 + ks * 16 + cp;
                    uint32_t b0 = *reinterpret_cast<const uint32_t*>(Br);
                    uint32_t b1 = *reinterpret_cast<const uint32_t*>(Br + 8);
                    mma16816(acc[nt], a0, a1, a2, a3, b0, b1);
                }
            }
        } else {
#pragma unroll
            for (int ks = 0; ks < 4; ks++) {
                const __nv_bfloat16* Ar = Ws + ((wid & 3) * 16 + r0) * 72 + ks * 16 + cp;
                uint32_t a0 = *reinterpret_cast<const uint32_t*>(Ar);
                uint32_t a1 = *reinterpret_cast<const uint32_t*>(Ar + 8 * 72);
                uint32_t a2 = *reinterpret_cast<const uint32_t*>(Ar + 8);
                uint32_t a3 = *reinterpret_cast<const uint32_t*>(Ar + 8 * 72 + 8);
#pragma unroll
                for (int nt = 0; nt < 8; nt++) {
                    const __nv_bfloat16* Br = XTs + ((wid >> 2) * 64 + nt * 8 + r0) * 72 + ks * 16 + cp;
                    uint32_t b0 = *reinterpret_cast<const uint32_t*>(Br);
                    uint32_t b1 = *reinterpret_cast<const uint32_t*>(Br + 8);
                    mma16816(acc[nt], a0, a1, a2, a3, b0, b1);
                }
            }
        }
        __syncthreads();
    }

    if (!is_v) {
        float qs = (role < 4) ? 0.09016844f : 1.0f;   // (1/16)*log2(e) folded into q
        int row = wid * 16 + r0;
#pragma unroll
        for (int nt = 0; nt < 8; nt++) {
            int col = nt * 8 + cp;
            *reinterpret_cast<uint32_t*>(&XTs[row * 72 + col])       = pack_bf16(acc[nt][0] * qs, acc[nt][1] * qs);
            *reinterpret_cast<uint32_t*>(&XTs[(row + 8) * 72 + col]) = pack_bf16(acc[nt][2] * qs, acc[nt][3] * qs);
        }
        __syncthreads();
        __nv_bfloat16* dst = (role < 4 ? g_qb : g_kb) + ((size_t)bh * NTOK + nx * 128) * 64;
#pragma unroll
        for (int i = 0; i < 4; i++) {
            int idx = tid + i * 256;
            int r = idx >> 3, c8 = idx & 7;
            *reinterpret_cast<uint4*>(dst + (size_t)r * 64 + c8 * 8) =
                *reinterpret_cast<uint4*>(&XTs[r * 72 + c8 * 8]);
        }
    } else {
        int chrow = (wid & 3) * 16 + r0;
#pragma unroll
        for (int nt = 0; nt < 8; nt++) {
            int col = (wid >> 2) * 64 + nt * 8 + cp;
            *reinterpret_cast<uint32_t*>(&XTs[chrow * 136 + col])       = pack_bf16(acc[nt][0], acc[nt][1]);
            *reinterpret_cast<uint32_t*>(&XTs[(chrow + 8) * 136 + col]) = pack_bf16(acc[nt][2], acc[nt][3]);
        }
        __syncthreads();
        __nv_bfloat16* dst = g_vb + (size_t)bh * HD * NTOK + nx * 128;
#pragma unroll
        for (int i = 0; i < 4; i++) {
            int idx = tid + i * 256;
            int r = idx >> 4, c16 = idx & 15;
            *reinterpret_cast<uint4*>(dst + (size_t)r * NTOK + c16 * 8) =
                *reinterpret_cast<uint4*>(&XTs[r * 136 + c16 * 8]);
        }
    }
}

// ---------------- HMMA flash attention (LDSM prefetch + split S chains) ----------------
#define AQ_SZ   (128 * 72)
#define AK_SZ   (128 * 72)
#define AV_SZ   (64 * 136)
#define STG_SZ  (AK_SZ + AV_SZ)
#define ATTN_SMEM ((AQ_SZ + 2 * STG_SZ) * 2)

__global__ __launch_bounds__(256, 2) void attn_mma_kernel() {
    extern __shared__ __nv_bfloat16 sm[];
    __nv_bfloat16* Qsm = sm;

    int tid = threadIdx.x, wid = tid >> 5, lane = tid & 31;
    int qb = blockIdx.x, bh = blockIdx.y;

    uint32_t sbase = smem_u32(sm);
    uint32_t Qb = sbase;
    uint32_t Kb[2] = {sbase + AQ_SZ * 2, sbase + (AQ_SZ + STG_SZ) * 2};
    uint32_t Vb[2] = {Kb[0] + AK_SZ * 2, Kb[1] + AK_SZ * 2};

    const __nv_bfloat16* Kg_base = g_kb + (size_t)bh * NTOK * 64;
    const __nv_bfloat16* Vg_base = g_vb + (size_t)bh * 64 * NTOK;

    auto load_kv = [&](int kb, int st) {
#pragma unroll
        for (int i = 0; i < 4; i++) {
            int idx = tid + i * 256;
            int r = idx >> 3, c8 = idx & 7;
            cp16(Kb[st] + (r * 72 + c8 * 8) * 2,
                 Kg_base + ((size_t)(kb * 128 + r)) * 64 + c8 * 8);
        }
#pragma unroll
        for (int i = 0; i < 4; i++) {
            int idx = tid + i * 256;
            int r = idx >> 4, c16 = idx & 15;
            cp16(Vb[st] + (r * 136 + c16 * 8) * 2,
                 Vg_base + (size_t)r * NTOK + kb * 128 + c16 * 8);
        }
    };

    {
        const uint4* Qg = reinterpret_cast<const uint4*>(g_qb + ((size_t)bh * NTOK + qb * 128) * 64);
#pragma unroll
        for (int i = 0; i < 4; i++) {
            int idx = tid + i * 256;
            int r = idx >> 3, c8 = idx & 7;
            *reinterpret_cast<uint4*>(Qsm + r * 72 + c8 * 8) = Qg[idx];
        }
    }
    load_kv(0, 0);
    CP_COMMIT();
    __syncthreads();

    uint32_t qf[4][4];
#pragma unroll
    for (int ks = 0; ks < 4; ks++) {
        uint32_t addr = Qb + ((wid * 16 + (lane & 15)) * 72 + ks * 16 + (lane >> 4) * 8) * 2;
        ldsm_x4(qf[ks][0], qf[ks][1], qf[ks][2], qf[ks][3], addr);
    }

    float oacc[8][4] = {};
    float l0 = 0.f, l1 = 0.f;

    int btok = ((lane >> 4) << 3) + (lane & 7);
    int bk8  = lane & 8;

    for (int kb = 0; kb < 32; kb++) {
        int st = kb & 1;
        CP_WAIT(0);
        __syncthreads();
        if (kb + 1 < 32) { load_kv(kb + 1, st ^ 1); CP_COMMIT(); }

        // preload K frags for kt=0
        uint32_t kf[4][4];
        {
            uint32_t ka = Kb[st] + (btok * 72 + bk8) * 2;
#pragma unroll
            for (int ks = 0; ks < 4; ks++)
                ldsm_x4(kf[ks][0], kf[ks][1], kf[ks][2], kf[ks][3], ka + ks * 32);
        }

#pragma unroll
        for (int kt = 0; kt < 8; kt++) {
            // prefetch V frags for THIS kt (consumed after softmax -> latency hidden)
            uint32_t vf[4][4];
            {
                uint32_t va = Vb[st] + (btok * 136 + kt * 16 + bk8) * 2;
#pragma unroll
                for (int j = 0; j < 4; j++)
                    ldsm_x4(vf[j][0], vf[j][1], vf[j][2], vf[j][3], va + j * 16 * 136 * 2);
            }

            // S MMAs: two independent chains per accumulator (depth 2 instead of 4)
            float s0a[4] = {}, s1a[4] = {}, s0b[4] = {}, s1b[4] = {};
            mma16816(s0a, qf[0][0], qf[0][1], qf[0][2], qf[0][3], kf[0][0], kf[0][1]);
            mma16816(s1a, qf[0][0], qf[0][1], qf[0][2], qf[0][3], kf[0][2], kf[0][3]);
            mma16816(s0b, qf[1][0], qf[1][1], qf[1][2], qf[1][3], kf[1][0], kf[1][1]);
            mma16816(s1b, qf[1][0], qf[1][1], qf[1][2], qf[1][3], kf[1][2], kf[1][3]);
            mma16816(s0a, qf[2][0], qf[2][1], qf[2][2], qf[2][3], kf[2][0], kf[2][1]);
            mma16816(s1a, qf[2][0], qf[2][1], qf[2][2], qf[2][3], kf[2][2], kf[2][3]);
            mma16816(s0b, qf[3][0], qf[3][1], qf[3][2], qf[3][3], kf[3][0], kf[3][1]);
            mma16816(s1b, qf[3][0], qf[3][1], qf[3][2], qf[3][3], kf[3][2], kf[3][3]);

            // prefetch K frags for kt+1 (consumed after softmax+PV -> latency hidden)
            if (kt + 1 < 8) {
                uint32_t ka = Kb[st] + (((kt + 1) * 16 + btok) * 72 + bk8) * 2;
#pragma unroll
                for (int ks = 0; ks < 4; ks++)
                    ldsm_x4(kf[ks][0], kf[ks][1], kf[ks][2], kf[ks][3], ka + ks * 32);
            }

            // softmax (bounded logits; q pre-scaled)
            float p0 = ex2(s0a[0] + s0b[0]), p1 = ex2(s0a[1] + s0b[1]);
            float p2 = ex2(s0a[2] + s0b[2]), p3 = ex2(s0a[3] + s0b[3]);
            float p4 = ex2(s1a[0] + s1b[0]), p5 = ex2(s1a[1] + s1b[1]);
            float p6 = ex2(s1a[2] + s1b[2]), p7 = ex2(s1a[3] + s1b[3]);
            l0 += p0 + p1 + p4 + p5;
            l1 += p2 + p3 + p6 + p7;
            uint32_t a0 = pack_bf16(p0, p1), a1 = pack_bf16(p2, p3);
            uint32_t a2 = pack_bf16(p4, p5), a3 = pack_bf16(p6, p7);

            // PV MMAs with prefetched V frags
#pragma unroll
            for (int j = 0; j < 4; j++) {
                mma16816(oacc[2 * j],     a0, a1, a2, a3, vf[j][0], vf[j][1]);
                mma16816(oacc[2 * j + 1], a0, a1, a2, a3, vf[j][2], vf[j][3]);
            }
        }
    }

    l0 += __shfl_xor_sync(0xffffffffu, l0, 1);
    l0 += __shfl_xor_sync(0xffffffffu, l0, 2);
    l1 += __shfl_xor_sync(0xffffffffu, l1, 1);
    l1 += __shfl_xor_sync(0xffffffffu, l1, 2);
    float inv0 = 1.f / l0, inv1 = 1.f / l1;

    __syncthreads();
    int r0 = lane >> 2, cpair = (lane & 3) << 1;
    {
        int row = wid * 16 + r0;
#pragma unroll
        for (int nt = 0; nt < 8; nt++) {
            int col = nt * 8 + cpair;
            *reinterpret_cast<uint32_t*>(&Qsm[row * 72 + col])       = pack_bf16(oacc[nt][0] * inv0, oacc[nt][1] * inv0);
            *reinterpret_cast<uint32_t*>(&Qsm[(row + 8) * 72 + col]) = pack_bf16(oacc[nt][2] * inv1, oacc[nt][3] * inv1);
        }
    }
    __syncthreads();
    {
        int b = bh >> 2, h = bh & 3;
        __nv_bfloat16* dst = g_ob + ((size_t)b * NTOK + qb * 128) * CC + h * 64;
#pragma unroll
        for (int i = 0; i < 4; i++) {
            int idx = tid + i * 256;
            int r = idx >> 3, c8 = idx & 7;
            *reinterpret_cast<uint4*>(dst + (size_t)r * CC + c8 * 8) =
                *reinterpret_cast<uint4*>(&Qsm[r * 72 + c8 * 8]);
        }
    }
}

// ---------------- output projection (HMMA) + bias + residual ----------------
__global__ __launch_bounds__(256) void out_kernel(const float* __restrict__ wout,
                                                  const float* __restrict__ wout_b,
                                                  const float* __restrict__ inp,
                                                  float* __restrict__ out) {
    __shared__ __nv_bfloat16 XTs[128 * 72];
    __shared__ __nv_bfloat16 Ws[64 * 72];

    int tid = threadIdx.x, wid = tid >> 5, lane = tid & 31;
    int r0 = lane >> 2, cp = (lane & 3) << 1;
    int nx = blockIdx.x, my = blockIdx.y, b = blockIdx.z;

    const float* W = wout + (size_t)my * 64 * CC;
    const __nv_bfloat16* X = g_ob + (size_t)b * NTOK * CC;

    float acc[8][4] = {};

    for (int k0 = 0; k0 < CC; k0 += 64) {
#pragma unroll
        for (int i = 0; i < 4; i++) {
            int idx = tid + i * 256;
            int r = idx >> 4, c4 = (idx & 15) << 2;
            float4 w4 = *reinterpret_cast<const float4*>(W + (size_t)r * CC + k0 + c4);
            *reinterpret_cast<uint32_t*>(&Ws[r * 72 + c4])     = pack_bf16(w4.x, w4.y);
            *reinterpret_cast<uint32_t*>(&Ws[r * 72 + c4 + 2]) = pack_bf16(w4.z, w4.w);
        }
#pragma unroll
        for (int i = 0; i < 4; i++) {
            int idx = tid + i * 256;
            int r = idx >> 3, c8 = idx & 7;
            *reinterpret_cast<uint4*>(&XTs[r * 72 + c8 * 8]) =
                *reinterpret_cast<const uint4*>(X + ((size_t)(nx * 128 + r)) * CC + k0 + c8 * 8);
        }
        __syncthreads();
#pragma unroll
        for (int ks = 0; ks < 4; ks++) {
            const __nv_bfloat16* Ar = Ws + ((wid & 3) * 16 + r0) * 72 + ks * 16 + cp;
            uint32_t a0 = *reinterpret_cast<const uint32_t*>(Ar);
            uint32_t a1 = *reinterpret_cast<const uint32_t*>(Ar + 8 * 72);
            uint32_t a2 = *reinterpret_cast<const uint32_t*>(Ar + 8);
            uint32_t a3 = *reinterpret_cast<const uint32_t*>(Ar + 8 * 72 + 8);
#pragma unroll
            for (int nt = 0; nt < 8; nt++) {
                const __nv_bfloat16* Br = XTs + ((wid >> 2) * 64 + nt * 8 + r0) * 72 + ks * 16 + cp;
                uint32_t b0 = *reinterpret_cast<const uint32_t*>(Br);
                uint32_t b1 = *reinterpret_cast<const uint32_t*>(Br + 8);
                mma16816(acc[nt], a0, a1, a2, a3, b0, b1);
            }
        }
        __syncthreads();
    }

    {
        int ch0 = my * 64 + (wid & 3) * 16 + r0;
        float bias0 = wout_b[ch0], bias1 = wout_b[ch0 + 8];
#pragma unroll
        for (int nt = 0; nt < 8; nt++) {
            int col = nx * 128 + (wid >> 2) * 64 + nt * 8 + cp;
            size_t off0 = ((size_t)b * CC + ch0) * NTOK + col;
            size_t off1 = off0 + (size_t)8 * NTOK;
            float2 rin0 = *reinterpret_cast<const float2*>(inp + off0);
            float2 rin1 = *reinterpret_cast<const float2*>(inp + off1);
            float2 v0 = {acc[nt][0] + bias0 + rin0.x, acc[nt][1] + bias0 + rin0.y};
            float2 v1 = {acc[nt][2] + bias1 + rin1.x, acc[nt][3] + bias1 + rin1.y};
            *reinterpret_cast<float2*>(out + off0) = v0;
            *reinterpret_cast<float2*>(out + off1) = v1;
        }
    }
}

// ---------------- launch ----------------
extern "C" void kernel_launch(void* const* d_in, const int* in_sizes, int n_in,
                              void* d_out, int out_size) {
    const float* input  = (const float*)d_in[0];
    const float* cctx   = (const float*)d_in[1];
    const float* gn_w   = (const float*)d_in[2];
    const float* gn_b   = (const float*)d_in[3];
    const float* wq     = (const float*)d_in[4];
    const float* wkv    = (const float*)d_in[5];
    const float* wout_w = (const float*)d_in[6];
    const float* wout_b = (const float*)d_in[7];
    float* out = (float*)d_out;

    gn_xt_kernel<<<64, 256>>>(input, gn_w, gn_b, 0);
    gn_xt_kernel<<<64, 256>>>(cctx,  gn_w, gn_b, 1);
    qkv_kernel<<<dim3(32, 12, BB), 256>>>(wq, wkv);

    static int smem_set = 0;
    if (!smem_set) {
        cudaFuncSetAttribute(attn_mma_kernel, cudaFuncAttributeMaxDynamicSharedMemorySize, ATTN_SMEM);
        smem_set = 1;
    }
    attn_mma_kernel<<<dim3(32, BB * NHEAD), 256, ATTN_SMEM>>>();

    out_kernel<<<dim3(32, 4, BB), 256>>>(wout_w, wout_b, input, out);
}

// round 10
// speedup vs baseline: 1.0135x; 1.0135x over previous
#include <cuda_runtime.h>
#include <cuda_bf16.h>
#include <cstdint>

#define BB 2
#define CC 256
#define NHEAD 4
#define HD 64
#define NTOK 4096

// ---------------- device scratch ----------------
__device__ __nv_bfloat16 g_xq[BB*NTOK*CC];         // GN(input)^T  [b][tok][ch]
__device__ __nv_bfloat16 g_xk[BB*NTOK*CC];         // GN(c)^T      [b][tok][ch]
__device__ __nv_bfloat16 g_qb[BB*NHEAD*NTOK*HD];   // [bh][tok][d]  (pre-scaled by CEXP)
__device__ __nv_bfloat16 g_kb[BB*NHEAD*NTOK*HD];   // [bh][tok][d]
__device__ __nv_bfloat16 g_vb[BB*NHEAD*HD*NTOK];   // [bh][d][tok]
__device__ __nv_bfloat16 g_ob[BB*NTOK*CC];         // attn out     [b][tok][ch]

// ---------------- helpers ----------------
__device__ __forceinline__ void mma16816(float* c, uint32_t a0, uint32_t a1, uint32_t a2,
                                         uint32_t a3, uint32_t b0, uint32_t b1) {
    asm volatile(
        "mma.sync.aligned.m16n8k16.row.col.f32.bf16.bf16.f32 "
        "{%0,%1,%2,%3}, {%4,%5,%6,%7}, {%8,%9}, {%0,%1,%2,%3};"
        : "+f"(c[0]), "+f"(c[1]), "+f"(c[2]), "+f"(c[3])
        : "r"(a0), "r"(a1), "r"(a2), "r"(a3), "r"(b0), "r"(b1));
}
__device__ __forceinline__ float ex2(float x) {
    float r;
    asm("ex2.approx.ftz.f32 %0, %1;" : "=f"(r) : "f"(x));
    return r;
}
__device__ __forceinline__ uint32_t pack_bf16(float lo, float hi) {
    uint32_t r;
    asm("cvt.rn.bf16x2.f32 %0, %1, %2;" : "=r"(r) : "f"(hi), "f"(lo));
    return r;
}
__device__ __forceinline__ uint32_t smem_u32(const void* p) {
    uint32_t a;
    asm("{ .reg .u64 t; cvta.to.shared.u64 t, %1; cvt.u32.u64 %0, t; }" : "=r"(a) : "l"(p));
    return a;
}
__device__ __forceinline__ void ldsm_x4(uint32_t& r0, uint32_t& r1, uint32_t& r2, uint32_t& r3,
                                        uint32_t addr) {
    asm volatile("ldmatrix.sync.aligned.m8n8.x4.shared.b16 {%0,%1,%2,%3}, [%4];"
                 : "=r"(r0), "=r"(r1), "=r"(r2), "=r"(r3) : "r"(addr));
}
__device__ __forceinline__ void cp16(uint32_t saddr, const void* g) {
    asm volatile("cp.async.cg.shared.global [%0], [%1], 16;" :: "r"(saddr), "l"(g));
}
#define CP_COMMIT() asm volatile("cp.async.commit_group;" ::: "memory")
#define CP_WAIT(n)  asm volatile("cp.async.wait_group %0;" :: "n"(n) : "memory")

// ---------------- GroupNorm -> bf16 X^T [b][tok][256] ----------------
__global__ __launch_bounds__(256) void gn_xt_kernel(const float* __restrict__ src,
                                                    const float* __restrict__ gw,
                                                    const float* __restrict__ gb,
                                                    int which) {
    int b = blockIdx.x >> 5, g = blockIdx.x & 31;
    size_t base = ((size_t)b * CC + g * 8) * NTOK;
    const float4* s4 = reinterpret_cast<const float4*>(src + base);
    int tid = threadIdx.x;

    float sum = 0.f, ssq = 0.f;
#pragma unroll
    for (int i = 0; i < 32; i++) {
        float4 v = s4[tid + i * 256];
        sum += v.x + v.y + v.z + v.w;
        ssq += v.x * v.x + v.y * v.y + v.z * v.z + v.w * v.w;
    }
#pragma unroll
    for (int off = 16; off; off >>= 1) {
        sum += __shfl_xor_sync(0xffffffffu, sum, off);
        ssq += __shfl_xor_sync(0xffffffffu, ssq, off);
    }
    __shared__ float r1[8], r2[8];
    if ((tid & 31) == 0) { r1[tid >> 5] = sum; r2[tid >> 5] = ssq; }
    __syncthreads();
    sum = 0.f; ssq = 0.f;
#pragma unroll
    for (int i = 0; i < 8; i++) { sum += r1[i]; ssq += r2[i]; }
    float mean = sum * (1.f / 32768.f);
    float var  = ssq * (1.f / 32768.f) - mean * mean;
    float rstd = rsqrtf(var + 1e-5f);

    float a[8], c0[8];
#pragma unroll
    for (int ch = 0; ch < 8; ch++) {
        a[ch]  = gw[g * 8 + ch] * rstd;
        c0[ch] = gb[g * 8 + ch] - mean * a[ch];
    }
    __nv_bfloat16* xt = (which ? g_xk : g_xq) + (size_t)b * NTOK * CC + g * 8;
#pragma unroll
    for (int i = 0; i < 16; i++) {
        int tok = tid + i * 256;
        float v[8];
#pragma unroll
        for (int ch = 0; ch < 8; ch++)
            v[ch] = src[base + (size_t)ch * NTOK + tok] * a[ch] + c0[ch];
        uint4 u = {pack_bf16(v[0], v[1]), pack_bf16(v[2], v[3]),
                   pack_bf16(v[4], v[5]), pack_bf16(v[6], v[7])};
        *reinterpret_cast<uint4*>(xt + (size_t)tok * CC) = u;
    }
}

// ---------------- QKV projection via HMMA (q pre-scaled by CEXP) ----------------
__global__ __launch_bounds__(256) void qkv_kernel(const float* __restrict__ wq,
                                                  const float* __restrict__ wkv) {
    __shared__ __nv_bfloat16 XTs[128 * 72];
    __shared__ __nv_bfloat16 Ws[64 * 72];

    int tid = threadIdx.x, wid = tid >> 5, lane = tid & 31;
    int r0 = lane >> 2, cp = (lane & 3) << 1;
    int nx = blockIdx.x, role = blockIdx.y, b = blockIdx.z;

    const float* W;
    const __nv_bfloat16* X;
    int h;
    bool is_v = (role >= 8);
    if (role < 4)      { h = role;     W = wq  + (size_t)h * 64 * CC;          X = g_xq + (size_t)b * NTOK * CC; }
    else if (role < 8) { h = role - 4; W = wkv + (size_t)(h * 128) * CC;       X = g_xk + (size_t)b * NTOK * CC; }
    else               { h = role - 8; W = wkv + (size_t)(h * 128 + 64) * CC;  X = g_xk + (size_t)b * NTOK * CC; }
    int bh = b * NHEAD + h;

    float acc[8][4] = {};

    for (int k0 = 0; k0 < CC; k0 += 64) {
#pragma unroll
        for (int i = 0; i < 4; i++) {
            int idx = tid + i * 256;
            int r = idx >> 4, c4 = (idx & 15) << 2;
            float4 w4 = *reinterpret_cast<const float4*>(W + (size_t)r * CC + k0 + c4);
            *reinterpret_cast<uint32_t*>(&Ws[r * 72 + c4])     = pack_bf16(w4.x, w4.y);
            *reinterpret_cast<uint32_t*>(&Ws[r * 72 + c4 + 2]) = pack_bf16(w4.z, w4.w);
        }
#pragma unroll
        for (int i = 0; i < 4; i++) {
            int idx = tid + i * 256;
            int r = idx >> 3, c8 = idx & 7;
            *reinterpret_cast<uint4*>(&XTs[r * 72 + c8 * 8]) =
                *reinterpret_cast<const uint4*>(X + ((size_t)(nx * 128 + r)) * CC + k0 + c8 * 8);
        }
        __syncthreads();

        if (!is_v) {
#pragma unroll
            for (int ks = 0; ks < 4; ks++) {
                const __nv_bfloat16* Ar = XTs + (wid * 16 + r0) * 72 + ks * 16 + cp;
                uint32_t a0 = *reinterpret_cast<const uint32_t*>(Ar);
                uint32_t a1 = *reinterpret_cast<const uint32_t*>(Ar + 8 * 72);
                uint32_t a2 = *reinterpret_cast<const uint32_t*>(Ar + 8);
                uint32_t a3 = *reinterpret_cast<const uint32_t*>(Ar + 8 * 72 + 8);
#pragma unroll
                for (int nt = 0; nt < 8; nt++) {
                    const __nv_bfloat16* Br = Ws + (nt * 8 + r0) * 72 + ks * 16 + cp;
                    uint32_t b0 = *reinterpret_cast<const uint32_t*>(Br);
                    uint32_t b1 = *reinterpret_cast<const uint32_t*>(Br + 8);
                    mma16816(acc[nt], a0, a1, a2, a3, b0, b1);
                }
            }
        } else {
#pragma unroll
            for (int ks = 0; ks < 4; ks++) {
                const __nv_bfloat16* Ar = Ws + ((wid & 3) * 16 + r0) * 72 + ks * 16 + cp;
                uint32_t a0 = *reinterpret_cast<const uint32_t*>(Ar);
                uint32_t a1 = *reinterpret_cast<const uint32_t*>(Ar + 8 * 72);
                uint32_t a2 = *reinterpret_cast<const uint32_t*>(Ar + 8);
                uint32_t a3 = *reinterpret_cast<const uint32_t*>(Ar + 8 * 72 + 8);
#pragma unroll
                for (int nt = 0; nt < 8; nt++) {
                    const __nv_bfloat16* Br = XTs + ((wid >> 2) * 64 + nt * 8 + r0) * 72 + ks * 16 + cp;
                    uint32_t b0 = *reinterpret_cast<const uint32_t*>(Br);
                    uint32_t b1 = *reinterpret_cast<const uint32_t*>(Br + 8);
                    mma16816(acc[nt], a0, a1, a2, a3, b0, b1);
                }
            }
        }
        __syncthreads();
    }

    if (!is_v) {
        float qs = (role < 4) ? 0.09016844f : 1.0f;   // (1/16)*log2(e) folded into q
        int row = wid * 16 + r0;
#pragma unroll
        for (int nt = 0; nt < 8; nt++) {
            int col = nt * 8 + cp;
            *reinterpret_cast<uint32_t*>(&XTs[row * 72 + col])       = pack_bf16(acc[nt][0] * qs, acc[nt][1] * qs);
            *reinterpret_cast<uint32_t*>(&XTs[(row + 8) * 72 + col]) = pack_bf16(acc[nt][2] * qs, acc[nt][3] * qs);
        }
        __syncthreads();
        __nv_bfloat16* dst = (role < 4 ? g_qb : g_kb) + ((size_t)bh * NTOK + nx * 128) * 64;
#pragma unroll
        for (int i = 0; i < 4; i++) {
            int idx = tid + i * 256;
            int r = idx >> 3, c8 = idx & 7;
            *reinterpret_cast<uint4*>(dst + (size_t)r * 64 + c8 * 8) =
                *reinterpret_cast<uint4*>(&XTs[r * 72 + c8 * 8]);
        }
    } else {
        int chrow = (wid & 3) * 16 + r0;
#pragma unroll
        for (int nt = 0; nt < 8; nt++) {
            int col = (wid >> 2) * 64 + nt * 8 + cp;
            *reinterpret_cast<uint32_t*>(&XTs[chrow * 136 + col])       = pack_bf16(acc[nt][0], acc[nt][1]);
            *reinterpret_cast<uint32_t*>(&XTs[(chrow + 8) * 136 + col]) = pack_bf16(acc[nt][2], acc[nt][3]);
        }
        __syncthreads();
        __nv_bfloat16* dst = g_vb + (size_t)bh * HD * NTOK + nx * 128;
#pragma unroll
        for (int i = 0; i < 4; i++) {
            int idx = tid + i * 256;
            int r = idx >> 4, c16 = idx & 15;
            *reinterpret_cast<uint4*>(dst + (size_t)r * NTOK + c16 * 8) =
                *reinterpret_cast<uint4*>(&XTs[r * 136 + c16 * 8]);
        }
    }
}

// ---------------- HMMA flash attention (M=32/warp, 4 warps, halved LDSM traffic) ----------------
#define AQ_SZ   (128 * 72)
#define AK_SZ   (128 * 72)
#define AV_SZ   (64 * 136)
#define STG_SZ  (AK_SZ + AV_SZ)
#define ATTN_SMEM ((AQ_SZ + 2 * STG_SZ) * 2)

__global__ __launch_bounds__(128, 2) void attn_mma_kernel() {
    extern __shared__ __nv_bfloat16 sm[];
    __nv_bfloat16* Qsm = sm;

    int tid = threadIdx.x, wid = tid >> 5, lane = tid & 31;
    int qb = blockIdx.x, bh = blockIdx.y;

    uint32_t sbase = smem_u32(sm);
    uint32_t Qb = sbase;
    uint32_t Kb[2] = {sbase + AQ_SZ * 2, sbase + (AQ_SZ + STG_SZ) * 2};
    uint32_t Vb[2] = {Kb[0] + AK_SZ * 2, Kb[1] + AK_SZ * 2};

    const __nv_bfloat16* Kg_base = g_kb + (size_t)bh * NTOK * 64;
    const __nv_bfloat16* Vg_base = g_vb + (size_t)bh * 64 * NTOK;

    auto load_kv = [&](int kb, int st) {
#pragma unroll
        for (int i = 0; i < 8; i++) {
            int idx = tid + i * 128;
            int r = idx >> 3, c8 = idx & 7;
            cp16(Kb[st] + (r * 72 + c8 * 8) * 2,
                 Kg_base + ((size_t)(kb * 128 + r)) * 64 + c8 * 8);
        }
#pragma unroll
        for (int i = 0; i < 8; i++) {
            int idx = tid + i * 128;
            int r = idx >> 4, c16 = idx & 15;
            cp16(Vb[st] + (r * 136 + c16 * 8) * 2,
                 Vg_base + (size_t)r * NTOK + kb * 128 + c16 * 8);
        }
    };

    {
        const uint4* Qg = reinterpret_cast<const uint4*>(g_qb + ((size_t)bh * NTOK + qb * 128) * 64);
#pragma unroll
        for (int i = 0; i < 8; i++) {
            int idx = tid + i * 128;
            int r = idx >> 3, c8 = idx & 7;
            *reinterpret_cast<uint4*>(Qsm + r * 72 + c8 * 8) = Qg[idx];
        }
    }
    load_kv(0, 0);
    CP_COMMIT();
    __syncthreads();

    // Q fragments: 2 m-tiles of 16 rows each (warp owns rows wid*32 .. wid*32+31)
    uint32_t qf[2][4][4];
#pragma unroll
    for (int t = 0; t < 2; t++)
#pragma unroll
        for (int ks = 0; ks < 4; ks++) {
            uint32_t addr = Qb + ((wid * 32 + t * 16 + (lane & 15)) * 72 + ks * 16 + (lane >> 4) * 8) * 2;
            ldsm_x4(qf[t][ks][0], qf[t][ks][1], qf[t][ks][2], qf[t][ks][3], addr);
        }

    float oacc[2][8][4] = {};
    float l0[2] = {0.f, 0.f}, l1[2] = {0.f, 0.f};

    int btok = ((lane >> 4) << 3) + (lane & 7);
    int bk8  = lane & 8;

    for (int kb = 0; kb < 32; kb++) {
        int st = kb & 1;
        CP_WAIT(0);
        __syncthreads();
        if (kb + 1 < 32) { load_kv(kb + 1, st ^ 1); CP_COMMIT(); }

#pragma unroll
        for (int kt = 0; kt < 8; kt++) {
            // K frags for this slab (shared by both m-tiles -> halved LDSM traffic)
            uint32_t kf[4][4];
            {
                uint32_t ka = Kb[st] + ((kt * 16 + btok) * 72 + bk8) * 2;
#pragma unroll
                for (int ks = 0; ks < 4; ks++)
                    ldsm_x4(kf[ks][0], kf[ks][1], kf[ks][2], kf[ks][3], ka + ks * 32);
            }
            // V frags (shared by both m-tiles)
            uint32_t vf[4][4];
            {
                uint32_t va = Vb[st] + (btok * 136 + kt * 16 + bk8) * 2;
#pragma unroll
                for (int j = 0; j < 4; j++)
                    ldsm_x4(vf[j][0], vf[j][1], vf[j][2], vf[j][3], va + j * 16 * 136 * 2);
            }

            // S MMAs: 2 m-tiles x 2 n-halves, chains of 4
            float s[2][2][4] = {};
#pragma unroll
            for (int ks = 0; ks < 4; ks++) {
#pragma unroll
                for (int t = 0; t < 2; t++) {
                    mma16816(s[t][0], qf[t][ks][0], qf[t][ks][1], qf[t][ks][2], qf[t][ks][3], kf[ks][0], kf[ks][1]);
                    mma16816(s[t][1], qf[t][ks][0], qf[t][ks][1], qf[t][ks][2], qf[t][ks][3], kf[ks][2], kf[ks][3]);
                }
            }

            // softmax + PV per m-tile
#pragma unroll
            for (int t = 0; t < 2; t++) {
                float p0 = ex2(s[t][0][0]), p1 = ex2(s[t][0][1]);
                float p2 = ex2(s[t][0][2]), p3 = ex2(s[t][0][3]);
                float p4 = ex2(s[t][1][0]), p5 = ex2(s[t][1][1]);
                float p6 = ex2(s[t][1][2]), p7 = ex2(s[t][1][3]);
                l0[t] += p0 + p1 + p4 + p5;
                l1[t] += p2 + p3 + p6 + p7;
                uint32_t a0 = pack_bf16(p0, p1), a1 = pack_bf16(p2, p3);
                uint32_t a2 = pack_bf16(p4, p5), a3 = pack_bf16(p6, p7);
#pragma unroll
                for (int j = 0; j < 4; j++) {
                    mma16816(oacc[t][2 * j],     a0, a1, a2, a3, vf[j][0], vf[j][1]);
                    mma16816(oacc[t][2 * j + 1], a0, a1, a2, a3, vf[j][2], vf[j][3]);
                }
            }
        }
    }

#pragma unroll
    for (int t = 0; t < 2; t++) {
        l0[t] += __shfl_xor_sync(0xffffffffu, l0[t], 1);
        l0[t] += __shfl_xor_sync(0xffffffffu, l0[t], 2);
        l1[t] += __shfl_xor_sync(0xffffffffu, l1[t], 1);
        l1[t] += __shfl_xor_sync(0xffffffffu, l1[t], 2);
    }

    __syncthreads();
    int r0 = lane >> 2, cpair = (lane & 3) << 1;
#pragma unroll
    for (int t = 0; t < 2; t++) {
        float inv0 = 1.f / l0[t], inv1 = 1.f / l1[t];
        int row = wid * 32 + t * 16 + r0;
#pragma unroll
        for (int nt = 0; nt < 8; nt++) {
            int col = nt * 8 + cpair;
            *reinterpret_cast<uint32_t*>(&Qsm[row * 72 + col])       = pack_bf16(oacc[t][nt][0] * inv0, oacc[t][nt][1] * inv0);
            *reinterpret_cast<uint32_t*>(&Qsm[(row + 8) * 72 + col]) = pack_bf16(oacc[t][nt][2] * inv1, oacc[t][nt][3] * inv1);
        }
    }
    __syncthreads();
    {
        int b = bh >> 2, h = bh & 3;
        __nv_bfloat16* dst = g_ob + ((size_t)b * NTOK + qb * 128) * CC + h * 64;
#pragma unroll
        for (int i = 0; i < 8; i++) {
            int idx = tid + i * 128;
            int r = idx >> 3, c8 = idx & 7;
            *reinterpret_cast<uint4*>(dst + (size_t)r * CC + c8 * 8) =
                *reinterpret_cast<uint4*>(&Qsm[r * 72 + c8 * 8]);
        }
    }
}

// ---------------- output projection (HMMA) + bias + residual ----------------
__global__ __launch_bounds__(256) void out_kernel(const float* __restrict__ wout,
                                                  const float* __restrict__ wout_b,
                                                  const float* __restrict__ inp,
                                                  float* __restrict__ out) {
    __shared__ __nv_bfloat16 XTs[128 * 72];
    __shared__ __nv_bfloat16 Ws[64 * 72];

    int tid = threadIdx.x, wid = tid >> 5, lane = tid & 31;
    int r0 = lane >> 2, cp = (lane & 3) << 1;
    int nx = blockIdx.x, my = blockIdx.y, b = blockIdx.z;

    const float* W = wout + (size_t)my * 64 * CC;
    const __nv_bfloat16* X = g_ob + (size_t)b * NTOK * CC;

    float acc[8][4] = {};

    for (int k0 = 0; k0 < CC; k0 += 64) {
#pragma unroll
        for (int i = 0; i < 4; i++) {
            int idx = tid + i * 256;
            int r = idx >> 4, c4 = (idx & 15) << 2;
            float4 w4 = *reinterpret_cast<const float4*>(W + (size_t)r * CC + k0 + c4);
            *reinterpret_cast<uint32_t*>(&Ws[r * 72 + c4])     = pack_bf16(w4.x, w4.y);
            *reinterpret_cast<uint32_t*>(&Ws[r * 72 + c4 + 2]) = pack_bf16(w4.z, w4.w);
        }
#pragma unroll
        for (int i = 0; i < 4; i++) {
            int idx = tid + i * 256;
            int r = idx >> 3, c8 = idx & 7;
            *reinterpret_cast<uint4*>(&XTs[r * 72 + c8 * 8]) =
                *reinterpret_cast<const uint4*>(X + ((size_t)(nx * 128 + r)) * CC + k0 + c8 * 8);
        }
        __syncthreads();
#pragma unroll
        for (int ks = 0; ks < 4; ks++) {
            const __nv_bfloat16* Ar = Ws + ((wid & 3) * 16 + r0) * 72 + ks * 16 + cp;
            uint32_t a0 = *reinterpret_cast<const uint32_t*>(Ar);
            uint32_t a1 = *reinterpret_cast<const uint32_t*>(Ar + 8 * 72);
            uint32_t a2 = *reinterpret_cast<const uint32_t*>(Ar + 8);
            uint32_t a3 = *reinterpret_cast<const uint32_t*>(Ar + 8 * 72 + 8);
#pragma unroll
            for (int nt = 0; nt < 8; nt++) {
                const __nv_bfloat16* Br = XTs + ((wid >> 2) * 64 + nt * 8 + r0) * 72 + ks * 16 + cp;
                uint32_t b0 = *reinterpret_cast<const uint32_t*>(Br);
                uint32_t b1 = *reinterpret_cast<const uint32_t*>(Br + 8);
                mma16816(acc[nt], a0, a1, a2, a3, b0, b1);
            }
        }
        __syncthreads();
    }

    {
        int ch0 = my * 64 + (wid & 3) * 16 + r0;
        float bias0 = wout_b[ch0], bias1 = wout_b[ch0 + 8];
#pragma unroll
        for (int nt = 0; nt < 8; nt++) {
            int col = nx * 128 + (wid >> 2) * 64 + nt * 8 + cp;
            size_t off0 = ((size_t)b * CC + ch0) * NTOK + col;
            size_t off1 = off0 + (size_t)8 * NTOK;
            float2 rin0 = *reinterpret_cast<const float2*>(inp + off0);
            float2 rin1 = *reinterpret_cast<const float2*>(inp + off1);
            float2 v0 = {acc[nt][0] + bias0 + rin0.x, acc[nt][1] + bias0 + rin0.y};
            float2 v1 = {acc[nt][2] + bias1 + rin1.x, acc[nt][3] + bias1 + rin1.y};
            *reinterpret_cast<float2*>(out + off0) = v0;
            *reinterpret_cast<float2*>(out + off1) = v1;
        }
    }
}

// ---------------- launch ----------------
extern "C" void kernel_launch(void* const* d_in, const int* in_sizes, int n_in,
                              void* d_out, int out_size) {
    const float* input  = (const float*)d_in[0];
    const float* cctx   = (const float*)d_in[1];
    const float* gn_w   = (const float*)d_in[2];
    const float* gn_b   = (const float*)d_in[3];
    const float* wq     = (const float*)d_in[4];
    const float* wkv    = (const float*)d_in[5];
    const float* wout_w = (const float*)d_in[6];
    const float* wout_b = (const float*)d_in[7];
    float* out = (float*)d_out;

    gn_xt_kernel<<<64, 256>>>(input, gn_w, gn_b, 0);
    gn_xt_kernel<<<64, 256>>>(cctx,  gn_w, gn_b, 1);
    qkv_kernel<<<dim3(32, 12, BB), 256>>>(wq, wkv);

    static int smem_set = 0;
    if (!smem_set) {
        cudaFuncSetAttribute(attn_mma_kernel, cudaFuncAttributeMaxDynamicSharedMemorySize, ATTN_SMEM);
        smem_set = 1;
    }
    attn_mma_kernel<<<dim3(32, BB * NHEAD), 128, ATTN_SMEM>>>();

    out_kernel<<<dim3(32, 4, BB), 256>>>(wout_w, wout_b, input, out);
}

// round 11
// speedup vs baseline: 1.0722x; 1.0579x over previous
#include <cuda_runtime.h>
#include <cuda_fp16.h>
#include <cstdint>

#define BB 2
#define CC 256
#define NHEAD 4
#define HD 64
#define NTOK 4096

// ---------------- device scratch (fp16) ----------------
__device__ __half g_xq[BB*NTOK*CC];         // GN(input)^T  [b][tok][ch]
__device__ __half g_xk[BB*NTOK*CC];         // GN(c)^T      [b][tok][ch]
__device__ __half g_qb[BB*NHEAD*NTOK*HD];   // [bh][tok][d]  (pre-scaled by CEXP)
__device__ __half g_kb[BB*NHEAD*NTOK*HD];   // [bh][tok][d]
__device__ __half g_vb[BB*NHEAD*HD*NTOK];   // [bh][d][tok]
__device__ __half g_ob[BB*NTOK*CC];         // attn out     [b][tok][ch]

// ---------------- helpers ----------------
__device__ __forceinline__ void mma_f32(float* c, uint32_t a0, uint32_t a1, uint32_t a2,
                                        uint32_t a3, uint32_t b0, uint32_t b1) {
    asm volatile(
        "mma.sync.aligned.m16n8k16.row.col.f32.f16.f16.f32 "
        "{%0,%1,%2,%3}, {%4,%5,%6,%7}, {%8,%9}, {%0,%1,%2,%3};"
        : "+f"(c[0]), "+f"(c[1]), "+f"(c[2]), "+f"(c[3])
        : "r"(a0), "r"(a1), "r"(a2), "r"(a3), "r"(b0), "r"(b1));
}
__device__ __forceinline__ void mma_h16(uint32_t* c, uint32_t a0, uint32_t a1, uint32_t a2,
                                        uint32_t a3, uint32_t b0, uint32_t b1) {
    asm volatile(
        "mma.sync.aligned.m16n8k16.row.col.f16.f16.f16.f16 "
        "{%0,%1}, {%2,%3,%4,%5}, {%6,%7}, {%0,%1};"
        : "+r"(c[0]), "+r"(c[1])
        : "r"(a0), "r"(a1), "r"(a2), "r"(a3), "r"(b0), "r"(b1));
}
__device__ __forceinline__ uint32_t ex2h2(uint32_t x) {
    uint32_t r;
    asm("ex2.approx.f16x2 %0, %1;" : "=r"(r) : "r"(x));
    return r;
}
__device__ __forceinline__ uint32_t hadd2u(uint32_t a, uint32_t b) {
    uint32_t r;
    asm("add.f16x2 %0, %1, %2;" : "=r"(r) : "r"(a), "r"(b));
    return r;
}
__device__ __forceinline__ float2 h22f2(uint32_t u) {
    __half2 h = *reinterpret_cast<__half2*>(&u);
    return __half22float2(h);
}
__device__ __forceinline__ uint32_t packh2(float lo, float hi) {
    __half2 h = __floats2half2_rn(lo, hi);
    return *reinterpret_cast<uint32_t*>(&h);
}
__device__ __forceinline__ uint32_t smem_u32(const void* p) {
    uint32_t a;
    asm("{ .reg .u64 t; cvta.to.shared.u64 t, %1; cvt.u32.u64 %0, t; }" : "=r"(a) : "l"(p));
    return a;
}
__device__ __forceinline__ void ldsm_x4(uint32_t& r0, uint32_t& r1, uint32_t& r2, uint32_t& r3,
                                        uint32_t addr) {
    asm volatile("ldmatrix.sync.aligned.m8n8.x4.shared.b16 {%0,%1,%2,%3}, [%4];"
                 : "=r"(r0), "=r"(r1), "=r"(r2), "=r"(r3) : "r"(addr));
}
__device__ __forceinline__ void cp16(uint32_t saddr, const void* g) {
    asm volatile("cp.async.cg.shared.global [%0], [%1], 16;" :: "r"(saddr), "l"(g));
}
#define CP_COMMIT() asm volatile("cp.async.commit_group;" ::: "memory")
#define CP_WAIT(n)  asm volatile("cp.async.wait_group %0;" :: "n"(n) : "memory")

// ---------------- GroupNorm -> fp16 X^T [b][tok][256] ----------------
__global__ __launch_bounds__(256) void gn_xt_kernel(const float* __restrict__ src,
                                                    const float* __restrict__ gw,
                                                    const float* __restrict__ gb,
                                                    int which) {
    int b = blockIdx.x >> 5, g = blockIdx.x & 31;
    size_t base = ((size_t)b * CC + g * 8) * NTOK;
    const float4* s4 = reinterpret_cast<const float4*>(src + base);
    int tid = threadIdx.x;

    float sum = 0.f, ssq = 0.f;
#pragma unroll
    for (int i = 0; i < 32; i++) {
        float4 v = s4[tid + i * 256];
        sum += v.x + v.y + v.z + v.w;
        ssq += v.x * v.x + v.y * v.y + v.z * v.z + v.w * v.w;
    }
#pragma unroll
    for (int off = 16; off; off >>= 1) {
        sum += __shfl_xor_sync(0xffffffffu, sum, off);
        ssq += __shfl_xor_sync(0xffffffffu, ssq, off);
    }
    __shared__ float r1[8], r2[8];
    if ((tid & 31) == 0) { r1[tid >> 5] = sum; r2[tid >> 5] = ssq; }
    __syncthreads();
    sum = 0.f; ssq = 0.f;
#pragma unroll
    for (int i = 0; i < 8; i++) { sum += r1[i]; ssq += r2[i]; }
    float mean = sum * (1.f / 32768.f);
    float var  = ssq * (1.f / 32768.f) - mean * mean;
    float rstd = rsqrtf(var + 1e-5f);

    float a[8], c0[8];
#pragma unroll
    for (int ch = 0; ch < 8; ch++) {
        a[ch]  = gw[g * 8 + ch] * rstd;
        c0[ch] = gb[g * 8 + ch] - mean * a[ch];
    }
    __half* xt = (which ? g_xk : g_xq) + (size_t)b * NTOK * CC + g * 8;
#pragma unroll
    for (int i = 0; i < 16; i++) {
        int tok = tid + i * 256;
        float v[8];
#pragma unroll
        for (int ch = 0; ch < 8; ch++)
            v[ch] = src[base + (size_t)ch * NTOK + tok] * a[ch] + c0[ch];
        uint4 u = {packh2(v[0], v[1]), packh2(v[2], v[3]),
                   packh2(v[4], v[5]), packh2(v[6], v[7])};
        *reinterpret_cast<uint4*>(xt + (size_t)tok * CC) = u;
    }
}

// ---------------- QKV projection via HMMA (q pre-scaled by CEXP) ----------------
__global__ __launch_bounds__(256) void qkv_kernel(const float* __restrict__ wq,
                                                  const float* __restrict__ wkv) {
    __shared__ __half XTs[128 * 72];
    __shared__ __half Ws[64 * 72];

    int tid = threadIdx.x, wid = tid >> 5, lane = tid & 31;
    int r0 = lane >> 2, cp = (lane & 3) << 1;
    int nx = blockIdx.x, role = blockIdx.y, b = blockIdx.z;

    const float* W;
    const __half* X;
    int h;
    bool is_v = (role >= 8);
    if (role < 4)      { h = role;     W = wq  + (size_t)h * 64 * CC;          X = g_xq + (size_t)b * NTOK * CC; }
    else if (role < 8) { h = role - 4; W = wkv + (size_t)(h * 128) * CC;       X = g_xk + (size_t)b * NTOK * CC; }
    else               { h = role - 8; W = wkv + (size_t)(h * 128 + 64) * CC;  X = g_xk + (size_t)b * NTOK * CC; }
    int bh = b * NHEAD + h;

    float acc[8][4] = {};

    for (int k0 = 0; k0 < CC; k0 += 64) {
#pragma unroll
        for (int i = 0; i < 4; i++) {
            int idx = tid + i * 256;
            int r = idx >> 4, c4 = (idx & 15) << 2;
            float4 w4 = *reinterpret_cast<const float4*>(W + (size_t)r * CC + k0 + c4);
            *reinterpret_cast<uint32_t*>(&Ws[r * 72 + c4])     = packh2(w4.x, w4.y);
            *reinterpret_cast<uint32_t*>(&Ws[r * 72 + c4 + 2]) = packh2(w4.z, w4.w);
        }
#pragma unroll
        for (int i = 0; i < 4; i++) {
            int idx = tid + i * 256;
            int r = idx >> 3, c8 = idx & 7;
            *reinterpret_cast<uint4*>(&XTs[r * 72 + c8 * 8]) =
                *reinterpret_cast<const uint4*>(X + ((size_t)(nx * 128 + r)) * CC + k0 + c8 * 8);
        }
        __syncthreads();

        if (!is_v) {
#pragma unroll
            for (int ks = 0; ks < 4; ks++) {
                const __half* Ar = XTs + (wid * 16 + r0) * 72 + ks * 16 + cp;
                uint32_t a0 = *reinterpret_cast<const uint32_t*>(Ar);
                uint32_t a1 = *reinterpret_cast<const uint32_t*>(Ar + 8 * 72);
                uint32_t a2 = *reinterpret_cast<const uint32_t*>(Ar + 8);
                uint32_t a3 = *reinterpret_cast<const uint32_t*>(Ar + 8 * 72 + 8);
#pragma unroll
                for (int nt = 0; nt < 8; nt++) {
                    const __half* Br = Ws + (nt * 8 + r0) * 72 + ks * 16 + cp;
                    uint32_t b0 = *reinterpret_cast<const uint32_t*>(Br);
                    uint32_t b1 = *reinterpret_cast<const uint32_t*>(Br + 8);
                    mma_f32(acc[nt], a0, a1, a2, a3, b0, b1);
                }
            }
        } else {
#pragma unroll
            for (int ks = 0; ks < 4; ks++) {
                const __half* Ar = Ws + ((wid & 3) * 16 + r0) * 72 + ks * 16 + cp;
                uint32_t a0 = *reinterpret_cast<const uint32_t*>(Ar);
                uint32_t a1 = *reinterpret_cast<const uint32_t*>(Ar + 8 * 72);
                uint32_t a2 = *reinterpret_cast<const uint32_t*>(Ar + 8);
                uint32_t a3 = *reinterpret_cast<const uint32_t*>(Ar + 8 * 72 + 8);
#pragma unroll
                for (int nt = 0; nt < 8; nt++) {
                    const __half* Br = XTs + ((wid >> 2) * 64 + nt * 8 + r0) * 72 + ks * 16 + cp;
                    uint32_t b0 = *reinterpret_cast<const uint32_t*>(Br);
                    uint32_t b1 = *reinterpret_cast<const uint32_t*>(Br + 8);
                    mma_f32(acc[nt], a0, a1, a2, a3, b0, b1);
                }
            }
        }
        __syncthreads();
    }

    if (!is_v) {
        float qs = (role < 4) ? 0.09016844f : 1.0f;   // (1/16)*log2(e) folded into q
        int row = wid * 16 + r0;
#pragma unroll
        for (int nt = 0; nt < 8; nt++) {
            int col = nt * 8 + cp;
            *reinterpret_cast<uint32_t*>(&XTs[row * 72 + col])       = packh2(acc[nt][0] * qs, acc[nt][1] * qs);
            *reinterpret_cast<uint32_t*>(&XTs[(row + 8) * 72 + col]) = packh2(acc[nt][2] * qs, acc[nt][3] * qs);
        }
        __syncthreads();
        __half* dst = (role < 4 ? g_qb : g_kb) + ((size_t)bh * NTOK + nx * 128) * 64;
#pragma unroll
        for (int i = 0; i < 4; i++) {
            int idx = tid + i * 256;
            int r = idx >> 3, c8 = idx & 7;
            *reinterpret_cast<uint4*>(dst + (size_t)r * 64 + c8 * 8) =
                *reinterpret_cast<uint4*>(&XTs[r * 72 + c8 * 8]);
        }
    } else {
        int chrow = (wid & 3) * 16 + r0;
#pragma unroll
        for (int nt = 0; nt < 8; nt++) {
            int col = (wid >> 2) * 64 + nt * 8 + cp;
            *reinterpret_cast<uint32_t*>(&XTs[chrow * 136 + col])       = packh2(acc[nt][0], acc[nt][1]);
            *reinterpret_cast<uint32_t*>(&XTs[(chrow + 8) * 136 + col]) = packh2(acc[nt][2], acc[nt][3]);
        }
        __syncthreads();
        __half* dst = g_vb + (size_t)bh * HD * NTOK + nx * 128;
#pragma unroll
        for (int i = 0; i < 4; i++) {
            int idx = tid + i * 256;
            int r = idx >> 4, c16 = idx & 15;
            *reinterpret_cast<uint4*>(dst + (size_t)r * NTOK + c16 * 8) =
                *reinterpret_cast<uint4*>(&XTs[r * 136 + c16 * 8]);
        }
    }
}

// ---------------- HMMA flash attention (f16-accum S, ex2.f16x2 softmax) ----------------
#define AQ_SZ   (128 * 72)
#define AK_SZ   (128 * 72)
#define AV_SZ   (64 * 136)
#define STG_SZ  (AK_SZ + AV_SZ)
#define ATTN_SMEM ((AQ_SZ + 2 * STG_SZ) * 2)

__global__ __launch_bounds__(128, 2) void attn_mma_kernel() {
    extern __shared__ __half sm[];
    __half* Qsm = sm;

    int tid = threadIdx.x, wid = tid >> 5, lane = tid & 31;
    int qb = blockIdx.x, bh = blockIdx.y;

    uint32_t sbase = smem_u32(sm);
    uint32_t Qb = sbase;
    uint32_t Kb[2] = {sbase + AQ_SZ * 2, sbase + (AQ_SZ + STG_SZ) * 2};
    uint32_t Vb[2] = {Kb[0] + AK_SZ * 2, Kb[1] + AK_SZ * 2};

    const __half* Kg_base = g_kb + (size_t)bh * NTOK * 64;
    const __half* Vg_base = g_vb + (size_t)bh * 64 * NTOK;

    auto load_kv = [&](int kb, int st) {
#pragma unroll
        for (int i = 0; i < 8; i++) {
            int idx = tid + i * 128;
            int r = idx >> 3, c8 = idx & 7;
            cp16(Kb[st] + (r * 72 + c8 * 8) * 2,
                 Kg_base + ((size_t)(kb * 128 + r)) * 64 + c8 * 8);
        }
#pragma unroll
        for (int i = 0; i < 8; i++) {
            int idx = tid + i * 128;
            int r = idx >> 4, c16 = idx & 15;
            cp16(Vb[st] + (r * 136 + c16 * 8) * 2,
                 Vg_base + (size_t)r * NTOK + kb * 128 + c16 * 8);
        }
    };

    {
        const uint4* Qg = reinterpret_cast<const uint4*>(g_qb + ((size_t)bh * NTOK + qb * 128) * 64);
#pragma unroll
        for (int i = 0; i < 8; i++) {
            int idx = tid + i * 128;
            int r = idx >> 3, c8 = idx & 7;
            *reinterpret_cast<uint4*>(Qsm + r * 72 + c8 * 8) = Qg[idx];
        }
    }
    load_kv(0, 0);
    CP_COMMIT();
    __syncthreads();

    uint32_t qf[2][4][4];
#pragma unroll
    for (int t = 0; t < 2; t++)
#pragma unroll
        for (int ks = 0; ks < 4; ks++) {
            uint32_t addr = Qb + ((wid * 32 + t * 16 + (lane & 15)) * 72 + ks * 16 + (lane >> 4) * 8) * 2;
            ldsm_x4(qf[t][ks][0], qf[t][ks][1], qf[t][ks][2], qf[t][ks][3], addr);
        }

    float oacc[2][8][4] = {};
    float l0[2] = {0.f, 0.f}, l1[2] = {0.f, 0.f};

    int btok = ((lane >> 4) << 3) + (lane & 7);
    int bk8  = lane & 8;

    for (int kb = 0; kb < 32; kb++) {
        int st = kb & 1;
        CP_WAIT(0);
        __syncthreads();
        if (kb + 1 < 32) { load_kv(kb + 1, st ^ 1); CP_COMMIT(); }

#pragma unroll
        for (int kt = 0; kt < 8; kt++) {
            uint32_t kf[4][4];
            {
                uint32_t ka = Kb[st] + ((kt * 16 + btok) * 72 + bk8) * 2;
#pragma unroll
                for (int ks = 0; ks < 4; ks++)
                    ldsm_x4(kf[ks][0], kf[ks][1], kf[ks][2], kf[ks][3], ka + ks * 32);
            }
            uint32_t vf[4][4];
            {
                uint32_t va = Vb[st] + (btok * 136 + kt * 16 + bk8) * 2;
#pragma unroll
                for (int j = 0; j < 4; j++)
                    ldsm_x4(vf[j][0], vf[j][1], vf[j][2], vf[j][3], va + j * 16 * 136 * 2);
            }

            // S MMAs with f16 accumulators: s[t][n] = 2 regs {row r, row r+8}
            uint32_t s[2][2][2] = {};
#pragma unroll
            for (int ks = 0; ks < 4; ks++) {
#pragma unroll
                for (int t = 0; t < 2; t++) {
                    mma_h16(s[t][0], qf[t][ks][0], qf[t][ks][1], qf[t][ks][2], qf[t][ks][3], kf[ks][0], kf[ks][1]);
                    mma_h16(s[t][1], qf[t][ks][0], qf[t][ks][1], qf[t][ks][2], qf[t][ks][3], kf[ks][2], kf[ks][3]);
                }
            }

            // softmax: ex2 directly on packed f16x2 C-regs -> PV A-frags
#pragma unroll
            for (int t = 0; t < 2; t++) {
                uint32_t a0 = ex2h2(s[t][0][0]);   // row r,   k 0..7 pair
                uint32_t a1 = ex2h2(s[t][0][1]);   // row r+8, k 0..7 pair
                uint32_t a2 = ex2h2(s[t][1][0]);   // row r,   k 8..15 pair
                uint32_t a3 = ex2h2(s[t][1][1]);   // row r+8, k 8..15 pair
                float2 f0 = h22f2(hadd2u(a0, a2));
                float2 f1 = h22f2(hadd2u(a1, a3));
                l0[t] += f0.x + f0.y;
                l1[t] += f1.x + f1.y;
#pragma unroll
                for (int j = 0; j < 4; j++) {
                    mma_f32(oacc[t][2 * j],     a0, a1, a2, a3, vf[j][0], vf[j][1]);
                    mma_f32(oacc[t][2 * j + 1], a0, a1, a2, a3, vf[j][2], vf[j][3]);
                }
            }
        }
    }

#pragma unroll
    for (int t = 0; t < 2; t++) {
        l0[t] += __shfl_xor_sync(0xffffffffu, l0[t], 1);
        l0[t] += __shfl_xor_sync(0xffffffffu, l0[t], 2);
        l1[t] += __shfl_xor_sync(0xffffffffu, l1[t], 1);
        l1[t] += __shfl_xor_sync(0xffffffffu, l1[t], 2);
    }

    __syncthreads();
    int r0 = lane >> 2, cpair = (lane & 3) << 1;
#pragma unroll
    for (int t = 0; t < 2; t++) {
        float inv0 = 1.f / l0[t], inv1 = 1.f / l1[t];
        int row = wid * 32 + t * 16 + r0;
#pragma unroll
        for (int nt = 0; nt < 8; nt++) {
            int col = nt * 8 + cpair;
            *reinterpret_cast<uint32_t*>(&Qsm[row * 72 + col])       = packh2(oacc[t][nt][0] * inv0, oacc[t][nt][1] * inv0);
            *reinterpret_cast<uint32_t*>(&Qsm[(row + 8) * 72 + col]) = packh2(oacc[t][nt][2] * inv1, oacc[t][nt][3] * inv1);
        }
    }
    __syncthreads();
    {
        int b = bh >> 2, h = bh & 3;
        __half* dst = g_ob + ((size_t)b * NTOK + qb * 128) * CC + h * 64;
#pragma unroll
        for (int i = 0; i < 8; i++) {
            int idx = tid + i * 128;
            int r = idx >> 3, c8 = idx & 7;
            *reinterpret_cast<uint4*>(dst + (size_t)r * CC + c8 * 8) =
                *reinterpret_cast<uint4*>(&Qsm[r * 72 + c8 * 8]);
        }
    }
}

// ---------------- output projection (HMMA) + bias + residual ----------------
__global__ __launch_bounds__(256) void out_kernel(const float* __restrict__ wout,
                                                  const float* __restrict__ wout_b,
                                                  const float* __restrict__ inp,
                                                  float* __restrict__ out) {
    __shared__ __half XTs[128 * 72];
    __shared__ __half Ws[64 * 72];

    int tid = threadIdx.x, wid = tid >> 5, lane = tid & 31;
    int r0 = lane >> 2, cp = (lane & 3) << 1;
    int nx = blockIdx.x, my = blockIdx.y, b = blockIdx.z;

    const float* W = wout + (size_t)my * 64 * CC;
    const __half* X = g_ob + (size_t)b * NTOK * CC;

    float acc[8][4] = {};

    for (int k0 = 0; k0 < CC; k0 += 64) {
#pragma unroll
        for (int i = 0; i < 4; i++) {
            int idx = tid + i * 256;
            int r = idx >> 4, c4 = (idx & 15) << 2;
            float4 w4 = *reinterpret_cast<const float4*>(W + (size_t)r * CC + k0 + c4);
            *reinterpret_cast<uint32_t*>(&Ws[r * 72 + c4])     = packh2(w4.x, w4.y);
            *reinterpret_cast<uint32_t*>(&Ws[r * 72 + c4 + 2]) = packh2(w4.z, w4.w);
        }
#pragma unroll
        for (int i = 0; i < 4; i++) {
            int idx = tid + i * 256;
            int r = idx >> 3, c8 = idx & 7;
            *reinterpret_cast<uint4*>(&XTs[r * 72 + c8 * 8]) =
                *reinterpret_cast<const uint4*>(X + ((size_t)(nx * 128 + r)) * CC + k0 + c8 * 8);
        }
        __syncthreads();
#pragma unroll
        for (int ks = 0; ks < 4; ks++) {
            const __half* Ar = Ws + ((wid & 3) * 16 + r0) * 72 + ks * 16 + cp;
            uint32_t a0 = *reinterpret_cast<const uint32_t*>(Ar);
            uint32_t a1 = *reinterpret_cast<const uint32_t*>(Ar + 8 * 72);
            uint32_t a2 = *reinterpret_cast<const uint32_t*>(Ar + 8);
            uint32_t a3 = *reinterpret_cast<const uint32_t*>(Ar + 8 * 72 + 8);
#pragma unroll
            for (int nt = 0; nt < 8; nt++) {
                const __half* Br = XTs + ((wid >> 2) * 64 + nt * 8 + r0) * 72 + ks * 16 + cp;
                uint32_t b0 = *reinterpret_cast<const uint32_t*>(Br);
                uint32_t b1 = *reinterpret_cast<const uint32_t*>(Br + 8);
                mma_f32(acc[nt], a0, a1, a2, a3, b0, b1);
            }
        }
        __syncthreads();
    }

    {
        int ch0 = my * 64 + (wid & 3) * 16 + r0;
        float bias0 = wout_b[ch0], bias1 = wout_b[ch0 + 8];
#pragma unroll
        for (int nt = 0; nt < 8; nt++) {
            int col = nx * 128 + (wid >> 2) * 64 + nt * 8 + cp;
            size_t off0 = ((size_t)b * CC + ch0) * NTOK + col;
            size_t off1 = off0 + (size_t)8 * NTOK;
            float2 rin0 = *reinterpret_cast<const float2*>(inp + off0);
            float2 rin1 = *reinterpret_cast<const float2*>(inp + off1);
            float2 v0 = {acc[nt][0] + bias0 + rin0.x, acc[nt][1] + bias0 + rin0.y};
            float2 v1 = {acc[nt][2] + bias1 + rin1.x, acc[nt][3] + bias1 + rin1.y};
            *reinterpret_cast<float2*>(out + off0) = v0;
            *reinterpret_cast<float2*>(out + off1) = v1;
        }
    }
}

// ---------------- launch ----------------
extern "C" void kernel_launch(void* const* d_in, const int* in_sizes, int n_in,
                              void* d_out, int out_size) {
    const float* input  = (const float*)d_in[0];
    const float* cctx   = (const float*)d_in[1];
    const float* gn_w   = (const float*)d_in[2];
    const float* gn_b   = (const float*)d_in[3];
    const float* wq     = (const float*)d_in[4];
    const float* wkv    = (const float*)d_in[5];
    const float* wout_w = (const float*)d_in[6];
    const float* wout_b = (const float*)d_in[7];
    float* out = (float*)d_out;

    gn_xt_kernel<<<64, 256>>>(input, gn_w, gn_b, 0);
    gn_xt_kernel<<<64, 256>>>(cctx,  gn_w, gn_b, 1);
    qkv_kernel<<<dim3(32, 12, BB), 256>>>(wq, wkv);

    static int smem_set = 0;
    if (!smem_set) {
        cudaFuncSetAttribute(attn_mma_kernel, cudaFuncAttributeMaxDynamicSharedMemorySize, ATTN_SMEM);
        smem_set = 1;
    }
    attn_mma_kernel<<<dim3(32, BB * NHEAD), 128, ATTN_SMEM>>>();

    out_kernel<<<dim3(32, 4, BB), 256>>>(wout_w, wout_b, input, out);
}

// round 12
// speedup vs baseline: 1.0726x; 1.0004x over previous
#include <cuda_runtime.h>
#include <cuda_fp16.h>
#include <cstdint>

#define BB 2
#define CC 256
#define NHEAD 4
#define HD 64
#define NTOK 4096

// ---------------- device scratch (fp16) ----------------
__device__ __half g_xq[BB*NTOK*CC];         // GN(input)^T  [b][tok][ch]
__device__ __half g_xk[BB*NTOK*CC];         // GN(c)^T      [b][tok][ch]
__device__ __half g_qb[BB*NHEAD*NTOK*HD];   // [bh][tok][d]  (pre-scaled by CEXP)
__device__ __half g_kb[BB*NHEAD*NTOK*HD];   // [bh][tok][d]
__device__ __half g_vb[BB*NHEAD*HD*NTOK];   // [bh][d][tok]
__device__ __half g_ob[BB*NTOK*CC];         // attn out     [b][tok][ch]

// ---------------- helpers ----------------
__device__ __forceinline__ void mma_f32(float* c, uint32_t a0, uint32_t a1, uint32_t a2,
                                        uint32_t a3, uint32_t b0, uint32_t b1) {
    asm volatile(
        "mma.sync.aligned.m16n8k16.row.col.f32.f16.f16.f32 "
        "{%0,%1,%2,%3}, {%4,%5,%6,%7}, {%8,%9}, {%0,%1,%2,%3};"
        : "+f"(c[0]), "+f"(c[1]), "+f"(c[2]), "+f"(c[3])
        : "r"(a0), "r"(a1), "r"(a2), "r"(a3), "r"(b0), "r"(b1));
}
__device__ __forceinline__ void mma_h16(uint32_t* c, uint32_t a0, uint32_t a1, uint32_t a2,
                                        uint32_t a3, uint32_t b0, uint32_t b1) {
    asm volatile(
        "mma.sync.aligned.m16n8k16.row.col.f16.f16.f16.f16 "
        "{%0,%1}, {%2,%3,%4,%5}, {%6,%7}, {%0,%1};"
        : "+r"(c[0]), "+r"(c[1])
        : "r"(a0), "r"(a1), "r"(a2), "r"(a3), "r"(b0), "r"(b1));
}
__device__ __forceinline__ uint32_t ex2h2(uint32_t x) {
    uint32_t r;
    asm("ex2.approx.f16x2 %0, %1;" : "=r"(r) : "r"(x));
    return r;
}
__device__ __forceinline__ uint32_t hadd2u(uint32_t a, uint32_t b) {
    uint32_t r;
    asm("add.f16x2 %0, %1, %2;" : "=r"(r) : "r"(a), "r"(b));
    return r;
}
__device__ __forceinline__ float2 h22f2(uint32_t u) {
    __half2 h = *reinterpret_cast<__half2*>(&u);
    return __half22float2(h);
}
__device__ __forceinline__ uint32_t packh2(float lo, float hi) {
    __half2 h = __floats2half2_rn(lo, hi);
    return *reinterpret_cast<uint32_t*>(&h);
}
__device__ __forceinline__ uint32_t smem_u32(const void* p) {
    uint32_t a;
    asm("{ .reg .u64 t; cvta.to.shared.u64 t, %1; cvt.u32.u64 %0, t; }" : "=r"(a) : "l"(p));
    return a;
}
__device__ __forceinline__ void ldsm_x4(uint32_t& r0, uint32_t& r1, uint32_t& r2, uint32_t& r3,
                                        uint32_t addr) {
    asm volatile("ldmatrix.sync.aligned.m8n8.x4.shared.b16 {%0,%1,%2,%3}, [%4];"
                 : "=r"(r0), "=r"(r1), "=r"(r2), "=r"(r3) : "r"(addr));
}
__device__ __forceinline__ void cp16(uint32_t saddr, const void* g) {
    asm volatile("cp.async.cg.shared.global [%0], [%1], 16;" :: "r"(saddr), "l"(g));
}
#define CP_COMMIT() asm volatile("cp.async.commit_group;" ::: "memory")
#define CP_WAIT(n)  asm volatile("cp.async.wait_group %0;" :: "n"(n) : "memory")

// ---------------- GroupNorm -> fp16 X^T [b][tok][256] (fused both sources) ----------------
__global__ __launch_bounds__(256) void gn_xt_kernel(const float* __restrict__ src0,
                                                    const float* __restrict__ src1,
                                                    const float* __restrict__ gw,
                                                    const float* __restrict__ gb) {
    int which = blockIdx.y;
    const float* src = which ? src1 : src0;
    int b = blockIdx.x >> 5, g = blockIdx.x & 31;
    size_t base = ((size_t)b * CC + g * 8) * NTOK;
    const float4* s4 = reinterpret_cast<const float4*>(src + base);
    int tid = threadIdx.x;

    float sum = 0.f, ssq = 0.f;
#pragma unroll
    for (int i = 0; i < 32; i++) {
        float4 v = s4[tid + i * 256];
        sum += v.x + v.y + v.z + v.w;
        ssq += v.x * v.x + v.y * v.y + v.z * v.z + v.w * v.w;
    }
#pragma unroll
    for (int off = 16; off; off >>= 1) {
        sum += __shfl_xor_sync(0xffffffffu, sum, off);
        ssq += __shfl_xor_sync(0xffffffffu, ssq, off);
    }
    __shared__ float r1[8], r2[8];
    if ((tid & 31) == 0) { r1[tid >> 5] = sum; r2[tid >> 5] = ssq; }
    __syncthreads();
    sum = 0.f; ssq = 0.f;
#pragma unroll
    for (int i = 0; i < 8; i++) { sum += r1[i]; ssq += r2[i]; }
    float mean = sum * (1.f / 32768.f);
    float var  = ssq * (1.f / 32768.f) - mean * mean;
    float rstd = rsqrtf(var + 1e-5f);

    float a[8], c0[8];
#pragma unroll
    for (int ch = 0; ch < 8; ch++) {
        a[ch]  = gw[g * 8 + ch] * rstd;
        c0[ch] = gb[g * 8 + ch] - mean * a[ch];
    }
    __half* xt = (which ? g_xk : g_xq) + (size_t)b * NTOK * CC + g * 8;
#pragma unroll
    for (int i = 0; i < 16; i++) {
        int tok = tid + i * 256;
        float v[8];
#pragma unroll
        for (int ch = 0; ch < 8; ch++)
            v[ch] = src[base + (size_t)ch * NTOK + tok] * a[ch] + c0[ch];
        uint4 u = {packh2(v[0], v[1]), packh2(v[2], v[3]),
                   packh2(v[4], v[5]), packh2(v[6], v[7])};
        *reinterpret_cast<uint4*>(xt + (size_t)tok * CC) = u;
    }
}

// ---------------- QKV projection via HMMA (q pre-scaled by CEXP) ----------------
__global__ __launch_bounds__(256) void qkv_kernel(const float* __restrict__ wq,
                                                  const float* __restrict__ wkv) {
    __shared__ __half XTs[128 * 72];
    __shared__ __half Ws[64 * 72];

    int tid = threadIdx.x, wid = tid >> 5, lane = tid & 31;
    int r0 = lane >> 2, cp = (lane & 3) << 1;
    int nx = blockIdx.x, role = blockIdx.y, b = blockIdx.z;

    const float* W;
    const __half* X;
    int h;
    bool is_v = (role >= 8);
    if (role < 4)      { h = role;     W = wq  + (size_t)h * 64 * CC;          X = g_xq + (size_t)b * NTOK * CC; }
    else if (role < 8) { h = role - 4; W = wkv + (size_t)(h * 128) * CC;       X = g_xk + (size_t)b * NTOK * CC; }
    else               { h = role - 8; W = wkv + (size_t)(h * 128 + 64) * CC;  X = g_xk + (size_t)b * NTOK * CC; }
    int bh = b * NHEAD + h;

    float acc[8][4] = {};

    for (int k0 = 0; k0 < CC; k0 += 64) {
#pragma unroll
        for (int i = 0; i < 4; i++) {
            int idx = tid + i * 256;
            int r = idx >> 4, c4 = (idx & 15) << 2;
            float4 w4 = *reinterpret_cast<const float4*>(W + (size_t)r * CC + k0 + c4);
            *reinterpret_cast<uint32_t*>(&Ws[r * 72 + c4])     = packh2(w4.x, w4.y);
            *reinterpret_cast<uint32_t*>(&Ws[r * 72 + c4 + 2]) = packh2(w4.z, w4.w);
        }
#pragma unroll
        for (int i = 0; i < 4; i++) {
            int idx = tid + i * 256;
            int r = idx >> 3, c8 = idx & 7;
            *reinterpret_cast<uint4*>(&XTs[r * 72 + c8 * 8]) =
                *reinterpret_cast<const uint4*>(X + ((size_t)(nx * 128 + r)) * CC + k0 + c8 * 8);
        }
        __syncthreads();

        if (!is_v) {
#pragma unroll
            for (int ks = 0; ks < 4; ks++) {
                const __half* Ar = XTs + (wid * 16 + r0) * 72 + ks * 16 + cp;
                uint32_t a0 = *reinterpret_cast<const uint32_t*>(Ar);
                uint32_t a1 = *reinterpret_cast<const uint32_t*>(Ar + 8 * 72);
                uint32_t a2 = *reinterpret_cast<const uint32_t*>(Ar + 8);
                uint32_t a3 = *reinterpret_cast<const uint32_t*>(Ar + 8 * 72 + 8);
#pragma unroll
                for (int nt = 0; nt < 8; nt++) {
                    const __half* Br = Ws + (nt * 8 + r0) * 72 + ks * 16 + cp;
                    uint32_t b0 = *reinterpret_cast<const uint32_t*>(Br);
                    uint32_t b1 = *reinterpret_cast<const uint32_t*>(Br + 8);
                    mma_f32(acc[nt], a0, a1, a2, a3, b0, b1);
                }
            }
        } else {
#pragma unroll
            for (int ks = 0; ks < 4; ks++) {
                const __half* Ar = Ws + ((wid & 3) * 16 + r0) * 72 + ks * 16 + cp;
                uint32_t a0 = *reinterpret_cast<const uint32_t*>(Ar);
                uint32_t a1 = *reinterpret_cast<const uint32_t*>(Ar + 8 * 72);
                uint32_t a2 = *reinterpret_cast<const uint32_t*>(Ar + 8);
                uint32_t a3 = *reinterpret_cast<const uint32_t*>(Ar + 8 * 72 + 8);
#pragma unroll
                for (int nt = 0; nt < 8; nt++) {
                    const __half* Br = XTs + ((wid >> 2) * 64 + nt * 8 + r0) * 72 + ks * 16 + cp;
                    uint32_t b0 = *reinterpret_cast<const uint32_t*>(Br);
                    uint32_t b1 = *reinterpret_cast<const uint32_t*>(Br + 8);
                    mma_f32(acc[nt], a0, a1, a2, a3, b0, b1);
                }
            }
        }
        __syncthreads();
    }

    if (!is_v) {
        float qs = (role < 4) ? 0.09016844f : 1.0f;   // (1/16)*log2(e) folded into q
        int row = wid * 16 + r0;
#pragma unroll
        for (int nt = 0; nt < 8; nt++) {
            int col = nt * 8 + cp;
            *reinterpret_cast<uint32_t*>(&XTs[row * 72 + col])       = packh2(acc[nt][0] * qs, acc[nt][1] * qs);
            *reinterpret_cast<uint32_t*>(&XTs[(row + 8) * 72 + col]) = packh2(acc[nt][2] * qs, acc[nt][3] * qs);
        }
        __syncthreads();
        __half* dst = (role < 4 ? g_qb : g_kb) + ((size_t)bh * NTOK + nx * 128) * 64;
#pragma unroll
        for (int i = 0; i < 4; i++) {
            int idx = tid + i * 256;
            int r = idx >> 3, c8 = idx & 7;
            *reinterpret_cast<uint4*>(dst + (size_t)r * 64 + c8 * 8) =
                *reinterpret_cast<uint4*>(&XTs[r * 72 + c8 * 8]);
        }
    } else {
        int chrow = (wid & 3) * 16 + r0;
#pragma unroll
        for (int nt = 0; nt < 8; nt++) {
            int col = (wid >> 2) * 64 + nt * 8 + cp;
            *reinterpret_cast<uint32_t*>(&XTs[chrow * 136 + col])       = packh2(acc[nt][0], acc[nt][1]);
            *reinterpret_cast<uint32_t*>(&XTs[(chrow + 8) * 136 + col]) = packh2(acc[nt][2], acc[nt][3]);
        }
        __syncthreads();
        __half* dst = g_vb + (size_t)bh * HD * NTOK + nx * 128;
#pragma unroll
        for (int i = 0; i < 4; i++) {
            int idx = tid + i * 256;
            int r = idx >> 4, c16 = idx & 15;
            *reinterpret_cast<uint4*>(dst + (size_t)r * NTOK + c16 * 8) =
                *reinterpret_cast<uint4*>(&XTs[r * 136 + c16 * 8]);
        }
    }
}

// ---------------- HMMA flash attention (f16-accum S and PV; per-kb f32 spill) ----------------
#define AQ_SZ   (128 * 72)
#define AK_SZ   (128 * 72)
#define AV_SZ   (64 * 136)
#define STG_SZ  (AK_SZ + AV_SZ)
#define ATTN_SMEM ((AQ_SZ + 2 * STG_SZ) * 2)

__global__ __launch_bounds__(128, 2) void attn_mma_kernel() {
    extern __shared__ __half sm[];
    __half* Qsm = sm;

    int tid = threadIdx.x, wid = tid >> 5, lane = tid & 31;
    int qb = blockIdx.x, bh = blockIdx.y;

    uint32_t sbase = smem_u32(sm);
    uint32_t Qb = sbase;
    uint32_t Kb[2] = {sbase + AQ_SZ * 2, sbase + (AQ_SZ + STG_SZ) * 2};
    uint32_t Vb[2] = {Kb[0] + AK_SZ * 2, Kb[1] + AK_SZ * 2};

    const __half* Kg_base = g_kb + (size_t)bh * NTOK * 64;
    const __half* Vg_base = g_vb + (size_t)bh * 64 * NTOK;

    auto load_kv = [&](int kb, int st) {
#pragma unroll
        for (int i = 0; i < 8; i++) {
            int idx = tid + i * 128;
            int r = idx >> 3, c8 = idx & 7;
            cp16(Kb[st] + (r * 72 + c8 * 8) * 2,
                 Kg_base + ((size_t)(kb * 128 + r)) * 64 + c8 * 8);
        }
#pragma unroll
        for (int i = 0; i < 8; i++) {
            int idx = tid + i * 128;
            int r = idx >> 4, c16 = idx & 15;
            cp16(Vb[st] + (r * 136 + c16 * 8) * 2,
                 Vg_base + (size_t)r * NTOK + kb * 128 + c16 * 8);
        }
    };

    {
        const uint4* Qg = reinterpret_cast<const uint4*>(g_qb + ((size_t)bh * NTOK + qb * 128) * 64);
#pragma unroll
        for (int i = 0; i < 8; i++) {
            int idx = tid + i * 128;
            int r = idx >> 3, c8 = idx & 7;
            *reinterpret_cast<uint4*>(Qsm + r * 72 + c8 * 8) = Qg[idx];
        }
    }
    load_kv(0, 0);
    CP_COMMIT();
    __syncthreads();

    uint32_t qf[2][4][4];
#pragma unroll
    for (int t = 0; t < 2; t++)
#pragma unroll
        for (int ks = 0; ks < 4; ks++) {
            uint32_t addr = Qb + ((wid * 32 + t * 16 + (lane & 15)) * 72 + ks * 16 + (lane >> 4) * 8) * 2;
            ldsm_x4(qf[t][ks][0], qf[t][ks][1], qf[t][ks][2], qf[t][ks][3], addr);
        }

    float oacc[2][8][4] = {};
    float l0[2] = {0.f, 0.f}, l1[2] = {0.f, 0.f};

    int btok = ((lane >> 4) << 3) + (lane & 7);
    int bk8  = lane & 8;

    for (int kb = 0; kb < 32; kb++) {
        int st = kb & 1;
        CP_WAIT(0);
        __syncthreads();
        if (kb + 1 < 32) { load_kv(kb + 1, st ^ 1); CP_COMMIT(); }

        // per-block f16 PV accumulators (reset each kb)
        uint32_t op[2][8][2] = {};

#pragma unroll
        for (int kt = 0; kt < 8; kt++) {
            uint32_t kf[4][4];
            {
                uint32_t ka = Kb[st] + ((kt * 16 + btok) * 72 + bk8) * 2;
#pragma unroll
                for (int ks = 0; ks < 4; ks++)
                    ldsm_x4(kf[ks][0], kf[ks][1], kf[ks][2], kf[ks][3], ka + ks * 32);
            }
            uint32_t vf[4][4];
            {
                uint32_t va = Vb[st] + (btok * 136 + kt * 16 + bk8) * 2;
#pragma unroll
                for (int j = 0; j < 4; j++)
                    ldsm_x4(vf[j][0], vf[j][1], vf[j][2], vf[j][3], va + j * 16 * 136 * 2);
            }

            uint32_t s[2][2][2] = {};
#pragma unroll
            for (int ks = 0; ks < 4; ks++) {
#pragma unroll
                for (int t = 0; t < 2; t++) {
                    mma_h16(s[t][0], qf[t][ks][0], qf[t][ks][1], qf[t][ks][2], qf[t][ks][3], kf[ks][0], kf[ks][1]);
                    mma_h16(s[t][1], qf[t][ks][0], qf[t][ks][1], qf[t][ks][2], qf[t][ks][3], kf[ks][2], kf[ks][3]);
                }
            }

#pragma unroll
            for (int t = 0; t < 2; t++) {
                uint32_t a0 = ex2h2(s[t][0][0]);
                uint32_t a1 = ex2h2(s[t][0][1]);
                uint32_t a2 = ex2h2(s[t][1][0]);
                uint32_t a3 = ex2h2(s[t][1][1]);
                float2 f0 = h22f2(hadd2u(a0, a2));
                float2 f1 = h22f2(hadd2u(a1, a3));
                l0[t] += f0.x + f0.y;
                l1[t] += f1.x + f1.y;
#pragma unroll
                for (int j = 0; j < 4; j++) {
                    mma_h16(op[t][2 * j],     a0, a1, a2, a3, vf[j][0], vf[j][1]);
                    mma_h16(op[t][2 * j + 1], a0, a1, a2, a3, vf[j][2], vf[j][3]);
                }
            }
        }

        // spill f16 partials into f32 accumulators
#pragma unroll
        for (int t = 0; t < 2; t++)
#pragma unroll
            for (int nt = 0; nt < 8; nt++) {
                float2 f0 = h22f2(op[t][nt][0]);
                float2 f1 = h22f2(op[t][nt][1]);
                oacc[t][nt][0] += f0.x; oacc[t][nt][1] += f0.y;
                oacc[t][nt][2] += f1.x; oacc[t][nt][3] += f1.y;
            }
    }

#pragma unroll
    for (int t = 0; t < 2; t++) {
        l0[t] += __shfl_xor_sync(0xffffffffu, l0[t], 1);
        l0[t] += __shfl_xor_sync(0xffffffffu, l0[t], 2);
        l1[t] += __shfl_xor_sync(0xffffffffu, l1[t], 1);
        l1[t] += __shfl_xor_sync(0xffffffffu, l1[t], 2);
    }

    __syncthreads();
    int r0 = lane >> 2, cpair = (lane & 3) << 1;
#pragma unroll
    for (int t = 0; t < 2; t++) {
        float inv0 = 1.f / l0[t], inv1 = 1.f / l1[t];
        int row = wid * 32 + t * 16 + r0;
#pragma unroll
        for (int nt = 0; nt < 8; nt++) {
            int col = nt * 8 + cpair;
            *reinterpret_cast<uint32_t*>(&Qsm[row * 72 + col])       = packh2(oacc[t][nt][0] * inv0, oacc[t][nt][1] * inv0);
            *reinterpret_cast<uint32_t*>(&Qsm[(row + 8) * 72 + col]) = packh2(oacc[t][nt][2] * inv1, oacc[t][nt][3] * inv1);
        }
    }
    __syncthreads();
    {
        int b = bh >> 2, h = bh & 3;
        __half* dst = g_ob + ((size_t)b * NTOK + qb * 128) * CC + h * 64;
#pragma unroll
        for (int i = 0; i < 8; i++) {
            int idx = tid + i * 128;
            int r = idx >> 3, c8 = idx & 7;
            *reinterpret_cast<uint4*>(dst + (size_t)r * CC + c8 * 8) =
                *reinterpret_cast<uint4*>(&Qsm[r * 72 + c8 * 8]);
        }
    }
}

// ---------------- output projection (HMMA) + bias + residual ----------------
__global__ __launch_bounds__(256) void out_kernel(const float* __restrict__ wout,
                                                  const float* __restrict__ wout_b,
                                                  const float* __restrict__ inp,
                                                  float* __restrict__ out) {
    __shared__ __half XTs[128 * 72];
    __shared__ __half Ws[64 * 72];

    int tid = threadIdx.x, wid = tid >> 5, lane = tid & 31;
    int r0 = lane >> 2, cp = (lane & 3) << 1;
    int nx = blockIdx.x, my = blockIdx.y, b = blockIdx.z;

    const float* W = wout + (size_t)my * 64 * CC;
    const __half* X = g_ob + (size_t)b * NTOK * CC;

    float acc[8][4] = {};

    for (int k0 = 0; k0 < CC; k0 += 64) {
#pragma unroll
        for (int i = 0; i < 4; i++) {
            int idx = tid + i * 256;
            int r = idx >> 4, c4 = (idx & 15) << 2;
            float4 w4 = *reinterpret_cast<const float4*>(W + (size_t)r * CC + k0 + c4);
            *reinterpret_cast<uint32_t*>(&Ws[r * 72 + c4])     = packh2(w4.x, w4.y);
            *reinterpret_cast<uint32_t*>(&Ws[r * 72 + c4 + 2]) = packh2(w4.z, w4.w);
        }
#pragma unroll
        for (int i = 0; i < 4; i++) {
            int idx = tid + i * 256;
            int r = idx >> 3, c8 = idx & 7;
            *reinterpret_cast<uint4*>(&XTs[r * 72 + c8 * 8]) =
                *reinterpret_cast<const uint4*>(X + ((size_t)(nx * 128 + r)) * CC + k0 + c8 * 8);
        }
        __syncthreads();
#pragma unroll
        for (int ks = 0; ks < 4; ks++) {
            const __half* Ar = Ws + ((wid & 3) * 16 + r0) * 72 + ks * 16 + cp;
            uint32_t a0 = *reinterpret_cast<const uint32_t*>(Ar);
            uint32_t a1 = *reinterpret_cast<const uint32_t*>(Ar + 8 * 72);
            uint32_t a2 = *reinterpret_cast<const uint32_t*>(Ar + 8);
            uint32_t a3 = *reinterpret_cast<const uint32_t*>(Ar + 8 * 72 + 8);
#pragma unroll
            for (int nt = 0; nt < 8; nt++) {
                const __half* Br = XTs + ((wid >> 2) * 64 + nt * 8 + r0) * 72 + ks * 16 + cp;
                uint32_t b0 = *reinterpret_cast<const uint32_t*>(Br);
                uint32_t b1 = *reinterpret_cast<const uint32_t*>(Br + 8);
                mma_f32(acc[nt], a0, a1, a2, a3, b0, b1);
            }
        }
        __syncthreads();
    }

    {
        int ch0 = my * 64 + (wid & 3) * 16 + r0;
        float bias0 = wout_b[ch0], bias1 = wout_b[ch0 + 8];
#pragma unroll
        for (int nt = 0; nt < 8; nt++) {
            int col = nx * 128 + (wid >> 2) * 64 + nt * 8 + cp;
            size_t off0 = ((size_t)b * CC + ch0) * NTOK + col;
            size_t off1 = off0 + (size_t)8 * NTOK;
            float2 rin0 = *reinterpret_cast<const float2*>(inp + off0);
            float2 rin1 = *reinterpret_cast<const float2*>(inp + off1);
            float2 v0 = {acc[nt][0] + bias0 + rin0.x, acc[nt][1] + bias0 + rin0.y};
            float2 v1 = {acc[nt][2] + bias1 + rin1.x, acc[nt][3] + bias1 + rin1.y};
            *reinterpret_cast<float2*>(out + off0) = v0;
            *reinterpret_cast<float2*>(out + off1) = v1;
        }
    }
}

// ---------------- launch ----------------
extern "C" void kernel_launch(void* const* d_in, const int* in_sizes, int n_in,
                              void* d_out, int out_size) {
    const float* input  = (const float*)d_in[0];
    const float* cctx   = (const float*)d_in[1];
    const float* gn_w   = (const float*)d_in[2];
    const float* gn_b   = (const float*)d_in[3];
    const float* wq     = (const float*)d_in[4];
    const float* wkv    = (const float*)d_in[5];
    const float* wout_w = (const float*)d_in[6];
    const float* wout_b = (const float*)d_in[7];
    float* out = (float*)d_out;

    gn_xt_kernel<<<dim3(64, 2), 256>>>(input, cctx, gn_w, gn_b);
    qkv_kernel<<<dim3(32, 12, BB), 256>>>(wq, wkv);

    static int smem_set = 0;
    if (!smem_set) {
        cudaFuncSetAttribute(attn_mma_kernel, cudaFuncAttributeMaxDynamicSharedMemorySize, ATTN_SMEM);
        smem_set = 1;
    }
    attn_mma_kernel<<<dim3(32, BB * NHEAD), 128, ATTN_SMEM>>>();

    out_kernel<<<dim3(32, 4, BB), 256>>>(wout_w, wout_b, input, out);
}

// round 13
// speedup vs baseline: 1.0855x; 1.0120x over previous
#include <cuda_runtime.h>
#include <cuda_fp16.h>
#include <cstdint>

#define BB 2
#define CC 256
#define NHEAD 4
#define HD 64
#define NTOK 4096

// ---------------- device scratch (fp16) ----------------
__device__ __half g_xq[BB*NTOK*CC];         // GN(input)^T  [b][tok][ch]
__device__ __half g_xk[BB*NTOK*CC];         // GN(c)^T      [b][tok][ch]
__device__ __half g_qb[BB*NHEAD*NTOK*HD];   // [bh][tok][d]  (pre-scaled by CEXP)
__device__ __half g_kb[BB*NHEAD*NTOK*HD];   // [bh][tok][d]
__device__ __half g_vb[BB*NHEAD*HD*NTOK];   // [bh][d][tok]
__device__ __half g_ob[BB*NTOK*CC];         // attn out     [b][tok][ch]

// ---------------- helpers ----------------
__device__ __forceinline__ void mma_f32(float* c, uint32_t a0, uint32_t a1, uint32_t a2,
                                        uint32_t a3, uint32_t b0, uint32_t b1) {
    asm volatile(
        "mma.sync.aligned.m16n8k16.row.col.f32.f16.f16.f32 "
        "{%0,%1,%2,%3}, {%4,%5,%6,%7}, {%8,%9}, {%0,%1,%2,%3};"
        : "+f"(c[0]), "+f"(c[1]), "+f"(c[2]), "+f"(c[3])
        : "r"(a0), "r"(a1), "r"(a2), "r"(a3), "r"(b0), "r"(b1));
}
__device__ __forceinline__ void mma_h16(uint32_t* c, uint32_t a0, uint32_t a1, uint32_t a2,
                                        uint32_t a3, uint32_t b0, uint32_t b1) {
    asm volatile(
        "mma.sync.aligned.m16n8k16.row.col.f16.f16.f16.f16 "
        "{%0,%1}, {%2,%3,%4,%5}, {%6,%7}, {%0,%1};"
        : "+r"(c[0]), "+r"(c[1])
        : "r"(a0), "r"(a1), "r"(a2), "r"(a3), "r"(b0), "r"(b1));
}
__device__ __forceinline__ uint32_t ex2h2(uint32_t x) {
    uint32_t r;
    asm("ex2.approx.f16x2 %0, %1;" : "=r"(r) : "r"(x));
    return r;
}
__device__ __forceinline__ uint32_t hadd2u(uint32_t a, uint32_t b) {
    uint32_t r;
    asm("add.f16x2 %0, %1, %2;" : "=r"(r) : "r"(a), "r"(b));
    return r;
}
__device__ __forceinline__ float2 h22f2(uint32_t u) {
    __half2 h = *reinterpret_cast<__half2*>(&u);
    return __half22float2(h);
}
__device__ __forceinline__ uint32_t packh2(float lo, float hi) {
    __half2 h = __floats2half2_rn(lo, hi);
    return *reinterpret_cast<uint32_t*>(&h);
}
__device__ __forceinline__ uint32_t smem_u32(const void* p) {
    uint32_t a;
    asm("{ .reg .u64 t; cvta.to.shared.u64 t, %1; cvt.u32.u64 %0, t; }" : "=r"(a) : "l"(p));
    return a;
}
__device__ __forceinline__ void ldsm_x4(uint32_t& r0, uint32_t& r1, uint32_t& r2, uint32_t& r3,
                                        uint32_t addr) {
    asm volatile("ldmatrix.sync.aligned.m8n8.x4.shared.b16 {%0,%1,%2,%3}, [%4];"
                 : "=r"(r0), "=r"(r1), "=r"(r2), "=r"(r3) : "r"(addr));
}
__device__ __forceinline__ void cp16(uint32_t saddr, const void* g) {
    asm volatile("cp.async.cg.shared.global [%0], [%1], 16;" :: "r"(saddr), "l"(g));
}
#define CP_COMMIT() asm volatile("cp.async.commit_group;" ::: "memory")
#define CP_WAIT(n)  asm volatile("cp.async.wait_group %0;" :: "n"(n) : "memory")

// ---------------- GroupNorm -> fp16 X^T [b][tok][256] (fused both sources) ----------------
__global__ __launch_bounds__(256) void gn_xt_kernel(const float* __restrict__ src0,
                                                    const float* __restrict__ src1,
                                                    const float* __restrict__ gw,
                                                    const float* __restrict__ gb) {
    int which = blockIdx.y;
    const float* src = which ? src1 : src0;
    int b = blockIdx.x >> 5, g = blockIdx.x & 31;
    size_t base = ((size_t)b * CC + g * 8) * NTOK;
    const float4* s4 = reinterpret_cast<const float4*>(src + base);
    int tid = threadIdx.x;

    float sum = 0.f, ssq = 0.f;
#pragma unroll
    for (int i = 0; i < 32; i++) {
        float4 v = s4[tid + i * 256];
        sum += v.x + v.y + v.z + v.w;
        ssq += v.x * v.x + v.y * v.y + v.z * v.z + v.w * v.w;
    }
#pragma unroll
    for (int off = 16; off; off >>= 1) {
        sum += __shfl_xor_sync(0xffffffffu, sum, off);
        ssq += __shfl_xor_sync(0xffffffffu, ssq, off);
    }
    __shared__ float r1[8], r2[8];
    if ((tid & 31) == 0) { r1[tid >> 5] = sum; r2[tid >> 5] = ssq; }
    __syncthreads();
    sum = 0.f; ssq = 0.f;
#pragma unroll
    for (int i = 0; i < 8; i++) { sum += r1[i]; ssq += r2[i]; }
    float mean = sum * (1.f / 32768.f);
    float var  = ssq * (1.f / 32768.f) - mean * mean;
    float rstd = rsqrtf(var + 1e-5f);

    float a[8], c0[8];
#pragma unroll
    for (int ch = 0; ch < 8; ch++) {
        a[ch]  = gw[g * 8 + ch] * rstd;
        c0[ch] = gb[g * 8 + ch] - mean * a[ch];
    }
    __half* xt = (which ? g_xk : g_xq) + (size_t)b * NTOK * CC + g * 8;
#pragma unroll
    for (int i = 0; i < 16; i++) {
        int tok = tid + i * 256;
        float v[8];
#pragma unroll
        for (int ch = 0; ch < 8; ch++)
            v[ch] = src[base + (size_t)ch * NTOK + tok] * a[ch] + c0[ch];
        uint4 u = {packh2(v[0], v[1]), packh2(v[2], v[3]),
                   packh2(v[4], v[5]), packh2(v[6], v[7])};
        *reinterpret_cast<uint4*>(xt + (size_t)tok * CC) = u;
    }
}

// ---------------- QKV projection via HMMA (X tiles double-buffered via cp.async) ----------------
__global__ __launch_bounds__(256) void qkv_kernel(const float* __restrict__ wq,
                                                  const float* __restrict__ wkv) {
    __shared__ __half XTs[2][128 * 72];
    __shared__ __half Ws[64 * 72];

    int tid = threadIdx.x, wid = tid >> 5, lane = tid & 31;
    int r0 = lane >> 2, cp = (lane & 3) << 1;
    int nx = blockIdx.x, role = blockIdx.y, b = blockIdx.z;

    const float* W;
    const __half* X;
    int h;
    bool is_v = (role >= 8);
    if (role < 4)      { h = role;     W = wq  + (size_t)h * 64 * CC;          X = g_xq + (size_t)b * NTOK * CC; }
    else if (role < 8) { h = role - 4; W = wkv + (size_t)(h * 128) * CC;       X = g_xk + (size_t)b * NTOK * CC; }
    else               { h = role - 8; W = wkv + (size_t)(h * 128 + 64) * CC;  X = g_xk + (size_t)b * NTOK * CC; }
    int bh = b * NHEAD + h;

    uint32_t xbase[2] = {smem_u32(&XTs[0][0]), smem_u32(&XTs[1][0])};

    auto load_x = [&](int k0, int st) {
#pragma unroll
        for (int i = 0; i < 4; i++) {
            int idx = tid + i * 256;
            int r = idx >> 3, c8 = idx & 7;
            cp16(xbase[st] + (r * 72 + c8 * 8) * 2,
                 X + ((size_t)(nx * 128 + r)) * CC + k0 + c8 * 8);
        }
    };

    load_x(0, 0);
    CP_COMMIT();

    float acc[8][4] = {};

    for (int kc = 0; kc < 4; kc++) {
        int k0 = kc * 64, st = kc & 1;
        // W chunk (synchronous; L2-resident across nx-CTAs)
#pragma unroll
        for (int i = 0; i < 4; i++) {
            int idx = tid + i * 256;
            int r = idx >> 4, c4 = (idx & 15) << 2;
            float4 w4 = *reinterpret_cast<const float4*>(W + (size_t)r * CC + k0 + c4);
            *reinterpret_cast<uint32_t*>(&Ws[r * 72 + c4])     = packh2(w4.x, w4.y);
            *reinterpret_cast<uint32_t*>(&Ws[r * 72 + c4 + 2]) = packh2(w4.z, w4.w);
        }
        CP_WAIT(0);
        __syncthreads();
        if (kc + 1 < 4) { load_x(k0 + 64, st ^ 1); CP_COMMIT(); }

        const __half* Xc = &XTs[st][0];
        if (!is_v) {
#pragma unroll
            for (int ks = 0; ks < 4; ks++) {
                const __half* Ar = Xc + (wid * 16 + r0) * 72 + ks * 16 + cp;
                uint32_t a0 = *reinterpret_cast<const uint32_t*>(Ar);
                uint32_t a1 = *reinterpret_cast<const uint32_t*>(Ar + 8 * 72);
                uint32_t a2 = *reinterpret_cast<const uint32_t*>(Ar + 8);
                uint32_t a3 = *reinterpret_cast<const uint32_t*>(Ar + 8 * 72 + 8);
#pragma unroll
                for (int nt = 0; nt < 8; nt++) {
                    const __half* Br = Ws + (nt * 8 + r0) * 72 + ks * 16 + cp;
                    uint32_t b0 = *reinterpret_cast<const uint32_t*>(Br);
                    uint32_t b1 = *reinterpret_cast<const uint32_t*>(Br + 8);
                    mma_f32(acc[nt], a0, a1, a2, a3, b0, b1);
                }
            }
        } else {
#pragma unroll
            for (int ks = 0; ks < 4; ks++) {
                const __half* Ar = Ws + ((wid & 3) * 16 + r0) * 72 + ks * 16 + cp;
                uint32_t a0 = *reinterpret_cast<const uint32_t*>(Ar);
                uint32_t a1 = *reinterpret_cast<const uint32_t*>(Ar + 8 * 72);
                uint32_t a2 = *reinterpret_cast<const uint32_t*>(Ar + 8);
                uint32_t a3 = *reinterpret_cast<const uint32_t*>(Ar + 8 * 72 + 8);
#pragma unroll
                for (int nt = 0; nt < 8; nt++) {
                    const __half* Br = Xc + ((wid >> 2) * 64 + nt * 8 + r0) * 72 + ks * 16 + cp;
                    uint32_t b0 = *reinterpret_cast<const uint32_t*>(Br);
                    uint32_t b1 = *reinterpret_cast<const uint32_t*>(Br + 8);
                    mma_f32(acc[nt], a0, a1, a2, a3, b0, b1);
                }
            }
        }
        __syncthreads();   // Ws reused next iter
    }

    if (!is_v) {
        float qs = (role < 4) ? 0.09016844f : 1.0f;   // (1/16)*log2(e) folded into q
        __half* stage = &XTs[0][0];
        int row = wid * 16 + r0;
#pragma unroll
        for (int nt = 0; nt < 8; nt++) {
            int col = nt * 8 + cp;
            *reinterpret_cast<uint32_t*>(&stage[row * 72 + col])       = packh2(acc[nt][0] * qs, acc[nt][1] * qs);
            *reinterpret_cast<uint32_t*>(&stage[(row + 8) * 72 + col]) = packh2(acc[nt][2] * qs, acc[nt][3] * qs);
        }
        __syncthreads();
        __half* dst = (role < 4 ? g_qb : g_kb) + ((size_t)bh * NTOK + nx * 128) * 64;
#pragma unroll
        for (int i = 0; i < 4; i++) {
            int idx = tid + i * 256;
            int r = idx >> 3, c8 = idx & 7;
            *reinterpret_cast<uint4*>(dst + (size_t)r * 64 + c8 * 8) =
                *reinterpret_cast<uint4*>(&stage[r * 72 + c8 * 8]);
        }
    } else {
        __half* stage = &XTs[0][0];   // reused as [64][136]
        int chrow = (wid & 3) * 16 + r0;
#pragma unroll
        for (int nt = 0; nt < 8; nt++) {
            int col = (wid >> 2) * 64 + nt * 8 + cp;
            *reinterpret_cast<uint32_t*>(&stage[chrow * 136 + col])       = packh2(acc[nt][0], acc[nt][1]);
            *reinterpret_cast<uint32_t*>(&stage[(chrow + 8) * 136 + col]) = packh2(acc[nt][2], acc[nt][3]);
        }
        __syncthreads();
        __half* dst = g_vb + (size_t)bh * HD * NTOK + nx * 128;
#pragma unroll
        for (int i = 0; i < 4; i++) {
            int idx = tid + i * 256;
            int r = idx >> 4, c16 = idx & 15;
            *reinterpret_cast<uint4*>(dst + (size_t)r * NTOK + c16 * 8) =
                *reinterpret_cast<uint4*>(&stage[r * 136 + c16 * 8]);
        }
    }
}

// ---------------- HMMA flash attention (unchanged from round 12) ----------------
#define AQ_SZ   (128 * 72)
#define AK_SZ   (128 * 72)
#define AV_SZ   (64 * 136)
#define STG_SZ  (AK_SZ + AV_SZ)
#define ATTN_SMEM ((AQ_SZ + 2 * STG_SZ) * 2)

__global__ __launch_bounds__(128, 2) void attn_mma_kernel() {
    extern __shared__ __half sm[];
    __half* Qsm = sm;

    int tid = threadIdx.x, wid = tid >> 5, lane = tid & 31;
    int qb = blockIdx.x, bh = blockIdx.y;

    uint32_t sbase = smem_u32(sm);
    uint32_t Qb = sbase;
    uint32_t Kb[2] = {sbase + AQ_SZ * 2, sbase + (AQ_SZ + STG_SZ) * 2};
    uint32_t Vb[2] = {Kb[0] + AK_SZ * 2, Kb[1] + AK_SZ * 2};

    const __half* Kg_base = g_kb + (size_t)bh * NTOK * 64;
    const __half* Vg_base = g_vb + (size_t)bh * 64 * NTOK;

    auto load_kv = [&](int kb, int st) {
#pragma unroll
        for (int i = 0; i < 8; i++) {
            int idx = tid + i * 128;
            int r = idx >> 3, c8 = idx & 7;
            cp16(Kb[st] + (r * 72 + c8 * 8) * 2,
                 Kg_base + ((size_t)(kb * 128 + r)) * 64 + c8 * 8);
        }
#pragma unroll
        for (int i = 0; i < 8; i++) {
            int idx = tid + i * 128;
            int r = idx >> 4, c16 = idx & 15;
            cp16(Vb[st] + (r * 136 + c16 * 8) * 2,
                 Vg_base + (size_t)r * NTOK + kb * 128 + c16 * 8);
        }
    };

    {
        const uint4* Qg = reinterpret_cast<const uint4*>(g_qb + ((size_t)bh * NTOK + qb * 128) * 64);
#pragma unroll
        for (int i = 0; i < 8; i++) {
            int idx = tid + i * 128;
            int r = idx >> 3, c8 = idx & 7;
            *reinterpret_cast<uint4*>(Qsm + r * 72 + c8 * 8) = Qg[idx];
        }
    }
    load_kv(0, 0);
    CP_COMMIT();
    __syncthreads();

    uint32_t qf[2][4][4];
#pragma unroll
    for (int t = 0; t < 2; t++)
#pragma unroll
        for (int ks = 0; ks < 4; ks++) {
            uint32_t addr = Qb + ((wid * 32 + t * 16 + (lane & 15)) * 72 + ks * 16 + (lane >> 4) * 8) * 2;
            ldsm_x4(qf[t][ks][0], qf[t][ks][1], qf[t][ks][2], qf[t][ks][3], addr);
        }

    float oacc[2][8][4] = {};
    float l0[2] = {0.f, 0.f}, l1[2] = {0.f, 0.f};

    int btok = ((lane >> 4) << 3) + (lane & 7);
    int bk8  = lane & 8;

    for (int kb = 0; kb < 32; kb++) {
        int st = kb & 1;
        CP_WAIT(0);
        __syncthreads();
        if (kb + 1 < 32) { load_kv(kb + 1, st ^ 1); CP_COMMIT(); }

        uint32_t op[2][8][2] = {};

#pragma unroll
        for (int kt = 0; kt < 8; kt++) {
            uint32_t kf[4][4];
            {
                uint32_t ka = Kb[st] + ((kt * 16 + btok) * 72 + bk8) * 2;
#pragma unroll
                for (int ks = 0; ks < 4; ks++)
                    ldsm_x4(kf[ks][0], kf[ks][1], kf[ks][2], kf[ks][3], ka + ks * 32);
            }
            uint32_t vf[4][4];
            {
                uint32_t va = Vb[st] + (btok * 136 + kt * 16 + bk8) * 2;
#pragma unroll
                for (int j = 0; j < 4; j++)
                    ldsm_x4(vf[j][0], vf[j][1], vf[j][2], vf[j][3], va + j * 16 * 136 * 2);
            }

            uint32_t s[2][2][2] = {};
#pragma unroll
            for (int ks = 0; ks < 4; ks++) {
#pragma unroll
                for (int t = 0; t < 2; t++) {
                    mma_h16(s[t][0], qf[t][ks][0], qf[t][ks][1], qf[t][ks][2], qf[t][ks][3], kf[ks][0], kf[ks][1]);
                    mma_h16(s[t][1], qf[t][ks][0], qf[t][ks][1], qf[t][ks][2], qf[t][ks][3], kf[ks][2], kf[ks][3]);
                }
            }

#pragma unroll
            for (int t = 0; t < 2; t++) {
                uint32_t a0 = ex2h2(s[t][0][0]);
                uint32_t a1 = ex2h2(s[t][0][1]);
                uint32_t a2 = ex2h2(s[t][1][0]);
                uint32_t a3 = ex2h2(s[t][1][1]);
                float2 f0 = h22f2(hadd2u(a0, a2));
                float2 f1 = h22f2(hadd2u(a1, a3));
                l0[t] += f0.x + f0.y;
                l1[t] += f1.x + f1.y;
#pragma unroll
                for (int j = 0; j < 4; j++) {
                    mma_h16(op[t][2 * j],     a0, a1, a2, a3, vf[j][0], vf[j][1]);
                    mma_h16(op[t][2 * j + 1], a0, a1, a2, a3, vf[j][2], vf[j][3]);
                }
            }
        }

#pragma unroll
        for (int t = 0; t < 2; t++)
#pragma unroll
            for (int nt = 0; nt < 8; nt++) {
                float2 f0 = h22f2(op[t][nt][0]);
                float2 f1 = h22f2(op[t][nt][1]);
                oacc[t][nt][0] += f0.x; oacc[t][nt][1] += f0.y;
                oacc[t][nt][2] += f1.x; oacc[t][nt][3] += f1.y;
            }
    }

#pragma unroll
    for (int t = 0; t < 2; t++) {
        l0[t] += __shfl_xor_sync(0xffffffffu, l0[t], 1);
        l0[t] += __shfl_xor_sync(0xffffffffu, l0[t], 2);
        l1[t] += __shfl_xor_sync(0xffffffffu, l1[t], 1);
        l1[t] += __shfl_xor_sync(0xffffffffu, l1[t], 2);
    }

    __syncthreads();
    int r0 = lane >> 2, cpair = (lane & 3) << 1;
#pragma unroll
    for (int t = 0; t < 2; t++) {
        float inv0 = 1.f / l0[t], inv1 = 1.f / l1[t];
        int row = wid * 32 + t * 16 + r0;
#pragma unroll
        for (int nt = 0; nt < 8; nt++) {
            int col = nt * 8 + cpair;
            *reinterpret_cast<uint32_t*>(&Qsm[row * 72 + col])       = packh2(oacc[t][nt][0] * inv0, oacc[t][nt][1] * inv0);
            *reinterpret_cast<uint32_t*>(&Qsm[(row + 8) * 72 + col]) = packh2(oacc[t][nt][2] * inv1, oacc[t][nt][3] * inv1);
        }
    }
    __syncthreads();
    {
        int b = bh >> 2, h = bh & 3;
        __half* dst = g_ob + ((size_t)b * NTOK + qb * 128) * CC + h * 64;
#pragma unroll
        for (int i = 0; i < 8; i++) {
            int idx = tid + i * 128;
            int r = idx >> 3, c8 = idx & 7;
            *reinterpret_cast<uint4*>(dst + (size_t)r * CC + c8 * 8) =
                *reinterpret_cast<uint4*>(&Qsm[r * 72 + c8 * 8]);
        }
    }
}

// ---------------- output projection (HMMA, X double-buffered) + bias + residual ----------------
__global__ __launch_bounds__(256) void out_kernel(const float* __restrict__ wout,
                                                  const float* __restrict__ wout_b,
                                                  const float* __restrict__ inp,
                                                  float* __restrict__ out) {
    __shared__ __half XTs[2][128 * 72];
    __shared__ __half Ws[64 * 72];

    int tid = threadIdx.x, wid = tid >> 5, lane = tid & 31;
    int r0 = lane >> 2, cp = (lane & 3) << 1;
    int nx = blockIdx.x, my = blockIdx.y, b = blockIdx.z;

    const float* W = wout + (size_t)my * 64 * CC;
    const __half* X = g_ob + (size_t)b * NTOK * CC;

    uint32_t xbase[2] = {smem_u32(&XTs[0][0]), smem_u32(&XTs[1][0])};

    auto load_x = [&](int k0, int st) {
#pragma unroll
        for (int i = 0; i < 4; i++) {
            int idx = tid + i * 256;
            int r = idx >> 3, c8 = idx & 7;
            cp16(xbase[st] + (r * 72 + c8 * 8) * 2,
                 X + ((size_t)(nx * 128 + r)) * CC + k0 + c8 * 8);
        }
    };

    load_x(0, 0);
    CP_COMMIT();

    float acc[8][4] = {};

    for (int kc = 0; kc < 4; kc++) {
        int k0 = kc * 64, st = kc & 1;
#pragma unroll
        for (int i = 0; i < 4; i++) {
            int idx = tid + i * 256;
            int r = idx >> 4, c4 = (idx & 15) << 2;
            float4 w4 = *reinterpret_cast<const float4*>(W + (size_t)r * CC + k0 + c4);
            *reinterpret_cast<uint32_t*>(&Ws[r * 72 + c4])     = packh2(w4.x, w4.y);
            *reinterpret_cast<uint32_t*>(&Ws[r * 72 + c4 + 2]) = packh2(w4.z, w4.w);
        }
        CP_WAIT(0);
        __syncthreads();
        if (kc + 1 < 4) { load_x(k0 + 64, st ^ 1); CP_COMMIT(); }

        const __half* Xc = &XTs[st][0];
#pragma unroll
        for (int ks = 0; ks < 4; ks++) {
            const __half* Ar = Ws + ((wid & 3) * 16 + r0) * 72 + ks * 16 + cp;
            uint32_t a0 = *reinterpret_cast<const uint32_t*>(Ar);
            uint32_t a1 = *reinterpret_cast<const uint32_t*>(Ar + 8 * 72);
            uint32_t a2 = *reinterpret_cast<const uint32_t*>(Ar + 8);
            uint32_t a3 = *reinterpret_cast<const uint32_t*>(Ar + 8 * 72 + 8);
#pragma unroll
            for (int nt = 0; nt < 8; nt++) {
                const __half* Br = Xc + ((wid >> 2) * 64 + nt * 8 + r0) * 72 + ks * 16 + cp;
                uint32_t b0 = *reinterpret_cast<const uint32_t*>(Br);
                uint32_t b1 = *reinterpret_cast<const uint32_t*>(Br + 8);
                mma_f32(acc[nt], a0, a1, a2, a3, b0, b1);
            }
        }
        __syncthreads();
    }

    {
        int ch0 = my * 64 + (wid & 3) * 16 + r0;
        float bias0 = wout_b[ch0], bias1 = wout_b[ch0 + 8];
#pragma unroll
        for (int nt = 0; nt < 8; nt++) {
            int col = nx * 128 + (wid >> 2) * 64 + nt * 8 + cp;
            size_t off0 = ((size_t)b * CC + ch0) * NTOK + col;
            size_t off1 = off0 + (size_t)8 * NTOK;
            float2 rin0 = *reinterpret_cast<const float2*>(inp + off0);
            float2 rin1 = *reinterpret_cast<const float2*>(inp + off1);
            float2 v0 = {acc[nt][0] + bias0 + rin0.x, acc[nt][1] + bias0 + rin0.y};
            float2 v1 = {acc[nt][2] + bias1 + rin1.x, acc[nt][3] + bias1 + rin1.y};
            *reinterpret_cast<float2*>(out + off0) = v0;
            *reinterpret_cast<float2*>(out + off1) = v1;
        }
    }
}

// ---------------- launch ----------------
extern "C" void kernel_launch(void* const* d_in, const int* in_sizes, int n_in,
                              void* d_out, int out_size) {
    const float* input  = (const float*)d_in[0];
    const float* cctx   = (const float*)d_in[1];
    const float* gn_w   = (const float*)d_in[2];
    const float* gn_b   = (const float*)d_in[3];
    const float* wq     = (const float*)d_in[4];
    const float* wkv    = (const float*)d_in[5];
    const float* wout_w = (const float*)d_in[6];
    const float* wout_b = (const float*)d_in[7];
    float* out = (float*)d_out;

    gn_xt_kernel<<<dim3(64, 2), 256>>>(input, cctx, gn_w, gn_b);
    qkv_kernel<<<dim3(32, 12, BB), 256>>>(wq, wkv);

    static int smem_set = 0;
    if (!smem_set) {
        cudaFuncSetAttribute(attn_mma_kernel, cudaFuncAttributeMaxDynamicSharedMemorySize, ATTN_SMEM);
        smem_set = 1;
    }
    attn_mma_kernel<<<dim3(32, BB * NHEAD), 128, ATTN_SMEM>>>();

    out_kernel<<<dim3(32, 4, BB), 256>>>(wout_w, wout_b, input, out);
}